// round 11
// baseline (speedup 1.0000x reference)
#include <cuda_runtime.h>
#include <cuda_bf16.h>
#include <math.h>

#define NN   50000
#define EE   400000
#define INC  128
#define D1   256
#define HH   4
#define HD   64
#define GG   64
#define OUTC 10

// ---------------- scratch (device globals; no allocation allowed) ----------------
__device__ float    g_q   [(size_t)NN * D1];
__device__ float    g_k   [(size_t)NN * D1];
__device__ float    g_v   [(size_t)NN * D1];
__device__ float    g_skip[(size_t)NN * D1];
__device__ float    g_h   [(size_t)NN * D1];
__device__ int      g_deg [NN];
__device__ int      g_off [NN + 1];
__device__ int      g_cur [NN];
__device__ int      g_csrc[EE];
__device__ float    g_pool[(size_t)GG * D1];
__device__ float    g_cnt [GG];
// bf16 hi/lo split operands (packed 2 x bf16 per u32, k-contiguous)
__device__ unsigned g_Ahi[(size_t)NN * D1 / 2];
__device__ unsigned g_Alo[(size_t)NN * D1 / 2];
__device__ unsigned g_Wthi[4 * D1 * D1 / 2];
__device__ unsigned g_Wtlo[4 * D1 * D1 / 2];

__device__ __forceinline__ float eluf(float x) { return x > 0.f ? x : expm1f(x); }

__device__ __forceinline__ void cp_async16(void* smem_dst, const void* gmem_src)
{
    unsigned saddr = (unsigned)__cvta_generic_to_shared(smem_dst);
    asm volatile("cp.async.cg.shared.global [%0], [%1], 16;"
                 :: "r"(saddr), "l"(gmem_src));
}
__device__ __forceinline__ void cp_async_commit() { asm volatile("cp.async.commit_group;"); }
__device__ __forceinline__ void cp_async_wait0()  { asm volatile("cp.async.wait_group 0;" ::: "memory"); }

// ---------------- mma.sync helpers (sm_80-era PTX; valid on compute_103) ---------
__device__ __forceinline__ void ldsm_x4(unsigned addr, unsigned* r)
{
    asm volatile("ldmatrix.sync.aligned.m8n8.x4.shared.b16 {%0,%1,%2,%3}, [%4];"
                 : "=r"(r[0]), "=r"(r[1]), "=r"(r[2]), "=r"(r[3]) : "r"(addr));
}
__device__ __forceinline__ void ldsm_x2(unsigned addr, unsigned* r)
{
    asm volatile("ldmatrix.sync.aligned.m8n8.x2.shared.b16 {%0,%1}, [%2];"
                 : "=r"(r[0]), "=r"(r[1]) : "r"(addr));
}
__device__ __forceinline__ void mma_bf16(float* c, const unsigned* a, const unsigned* b)
{
    asm volatile("mma.sync.aligned.m16n8k16.row.col.f32.bf16.bf16.f32 "
                 "{%0,%1,%2,%3}, {%4,%5,%6,%7}, {%8,%9}, {%0,%1,%2,%3};"
                 : "+f"(c[0]), "+f"(c[1]), "+f"(c[2]), "+f"(c[3])
                 : "r"(a[0]), "r"(a[1]), "r"(a[2]), "r"(a[3]),
                   "r"(b[0]), "r"(b[1]));
}

// ---------------- fp32 -> bf16 hi/lo split (packed pairs) ----------------
__device__ __forceinline__ unsigned pack_bf16(__nv_bfloat16 a, __nv_bfloat16 b)
{
    return (unsigned)__bfloat16_as_ushort(a) | ((unsigned)__bfloat16_as_ushort(b) << 16);
}
__device__ __forceinline__ void split2(float x, float y, unsigned& hi, unsigned& lo)
{
    __nv_bfloat16 hx = __float2bfloat16(x), hy = __float2bfloat16(y);
    __nv_bfloat16 lx = __float2bfloat16(x - __bfloat162float(hx));
    __nv_bfloat16 ly = __float2bfloat16(y - __bfloat162float(hy));
    hi = pack_bf16(hx, hy);
    lo = pack_bf16(lx, ly);
}

__global__ void convA_kernel(const float* __restrict__ X, unsigned* __restrict__ Ahi,
                             unsigned* __restrict__ Alo, int n2)
{
    int i = blockIdx.x * blockDim.x + threadIdx.x;
    if (i >= n2) return;
    float2 x = ((const float2*)X)[i];
    unsigned hi, lo;
    split2(x.x, x.y, hi, lo);
    Ahi[i] = hi;
    Alo[i] = lo;
}

struct WPtrs { const float* W[4]; };

// transpose W[K,256] -> Wt[256,K] (K-major rows) with hi/lo bf16 split
__global__ void convW_kernel(WPtrs wp, unsigned* __restrict__ Wthi,
                             unsigned* __restrict__ Wtlo, int K)
{
    __shared__ float t[32][33];
    int wi = blockIdx.z;
    const float* __restrict__ W = wp.W[wi];
    int n0 = blockIdx.x * 32, k0 = blockIdx.y * 32;
    for (int r = threadIdx.y; r < 32; r += 8)
        t[r][threadIdx.x] = W[(size_t)(k0 + r) * D1 + n0 + threadIdx.x];
    __syncthreads();
    int tid2 = threadIdx.y * 32 + threadIdx.x;
    int K2 = K >> 1;
    for (int i = tid2; i < 32 * 16; i += 256) {
        int n = i >> 4, kp = i & 15;
        unsigned hi, lo;
        split2(t[2 * kp][n], t[2 * kp + 1][n], hi, lo);
        size_t o = (size_t)(wi * D1 + n0 + n) * K2 + (k0 >> 1) + kp;
        Wthi[o] = hi;
        Wtlo[o] = lo;
    }
}

// ---------------- HMMA GEMM: C[wi][M,256] = A[M,K] @ W[wi][K,256] + b ------------
struct TCOut {
    const float* bias[4];
    float*       C[4];
};

#define ROWB   48
#define SECB   (128 * ROWB)      // 6144
#define CHUNKB (4 * SECB)        // 24576
#define SMEM_MMA (2 * CHUNKB)    // 49152

__global__ __launch_bounds__(256)
void gemm_mma_kernel(const unsigned* __restrict__ Ahi, const unsigned* __restrict__ Alo,
                     const unsigned* __restrict__ Wthi, const unsigned* __restrict__ Wtlo,
                     TCOut pr, int M, int K)
{
    extern __shared__ __align__(16) char smem[];
    const int tid = threadIdx.x, lane = tid & 31, wid = tid >> 5;
    const int bm = blockIdx.x, wi = blockIdx.y >> 1, bn = blockIdx.y & 1;
    const int warp_m = wid & 1, warp_n = wid >> 1;
    const int K2 = K >> 1, nkb = K >> 4;
    const unsigned sbase = (unsigned)__cvta_generic_to_shared(smem);

    const unsigned* gptr[4];
    unsigned sdst[4];
#pragma unroll
    for (int t = 0; t < 4; t++) {
        int id = tid + t * 256;
        int sec = id >> 8, sid = id & 255, row = sid >> 1, q = sid & 1;
        sdst[t] = sec * SECB + row * ROWB + q * 16;
        size_t rb;
        const unsigned* base;
        if (sec < 2) {
            int grow = bm * 128 + row;
            if (grow >= M) grow = M - 1;
            rb = (size_t)grow * K2;
            base = (sec == 0) ? Ahi : Alo;
        } else {
            int n = bn * 128 + row;
            rb = (size_t)(wi * D1 + n) * K2;
            base = (sec == 2) ? Wthi : Wtlo;
        }
        gptr[t] = base + rb + q * 4;
    }

    unsigned aAh[4], aAl[4], aBh[4], aBl[4];
#pragma unroll
    for (int i = 0; i < 4; i++) {
        unsigned arow = warp_m * 64 + i * 16 + (lane & 15);
        unsigned aoff = arow * ROWB + ((lane >> 4) << 4);
        aAh[i] = sbase + aoff;
        aAl[i] = sbase + SECB + aoff;
        unsigned brow = warp_n * 32 + i * 8 + (lane & 7);
        unsigned boff = brow * ROWB + (((lane >> 3) & 1) << 4);
        aBh[i] = sbase + 2 * SECB + boff;
        aBl[i] = sbase + 3 * SECB + boff;
    }

    float acc[4][4][4];
#pragma unroll
    for (int i = 0; i < 4; i++)
#pragma unroll
        for (int j = 0; j < 4; j++)
#pragma unroll
            for (int e = 0; e < 4; e++) acc[i][j][e] = 0.f;

#pragma unroll
    for (int t = 0; t < 4; t++) cp_async16(smem + sdst[t], gptr[t]);
    cp_async_commit();

    for (int kb = 0; kb < nkb; kb++) {
        const int cur = kb & 1;
        cp_async_wait0();
        __syncthreads();
        if (kb + 1 < nkb) {
            const unsigned bo = (cur ^ 1) * CHUNKB;
            const int go = (kb + 1) * 8;
#pragma unroll
            for (int t = 0; t < 4; t++)
                cp_async16(smem + bo + sdst[t], gptr[t] + go);
            cp_async_commit();
        }

        const unsigned bo = cur * CHUNKB;
        unsigned Ah[4][4], Al[4][4], Bh[4][2], Bl[4][2];
#pragma unroll
        for (int i = 0; i < 4; i++) {
            ldsm_x4(aAh[i] + bo, Ah[i]);
            ldsm_x4(aAl[i] + bo, Al[i]);
            ldsm_x2(aBh[i] + bo, Bh[i]);
            ldsm_x2(aBl[i] + bo, Bl[i]);
        }
#pragma unroll
        for (int i = 0; i < 4; i++)
#pragma unroll
            for (int j = 0; j < 4; j++) {
                mma_bf16(acc[i][j], Ah[i], Bh[j]);
                mma_bf16(acc[i][j], Ah[i], Bl[j]);
                mma_bf16(acc[i][j], Al[i], Bh[j]);
            }
        __syncthreads();
    }

    const float* __restrict__ bias = pr.bias[wi];
    float* __restrict__ C = pr.C[wi];
    const int colbase = bn * 128 + warp_n * 32;
#pragma unroll
    for (int j = 0; j < 4; j++) {
        int c0 = colbase + j * 8 + (lane & 3) * 2;
        float bx = bias[c0], by = bias[c0 + 1];
#pragma unroll
        for (int i = 0; i < 4; i++) {
            int r0 = bm * 128 + warp_m * 64 + i * 16 + (lane >> 2);
            if (r0 < M) {
                float2 o = make_float2(acc[i][j][0] + bx, acc[i][j][1] + by);
                *(float2*)(C + (size_t)r0 * D1 + c0) = o;
            }
            int r1 = r0 + 8;
            if (r1 < M) {
                float2 o = make_float2(acc[i][j][2] + bx, acc[i][j][3] + by);
                *(float2*)(C + (size_t)r1 * D1 + c0) = o;
            }
        }
    }
}

// ---------------- CSR build (by dst), once per launch ----------------
__global__ void zero_deg_kernel(int* deg)
{
    int i = blockIdx.x * blockDim.x + threadIdx.x;
    if (i < NN) deg[i] = 0;
}

__global__ void hist_kernel(const int* __restrict__ dst, int* __restrict__ deg)
{
    int e = blockIdx.x * blockDim.x + threadIdx.x;
    if (e < EE) atomicAdd(&deg[dst[e]], 1);
}

__global__ void scan_kernel(const int* __restrict__ deg, int* __restrict__ off,
                            int* __restrict__ cur)
{
    __shared__ int sums[1024];
    const int C = (NN + 1023) / 1024;
    int t = threadIdx.x;
    int b0 = t * C, b1 = min(b0 + C, NN);
    int s = 0;
    for (int i = b0; i < b1; i++) s += deg[i];
    sums[t] = s;
    __syncthreads();
    for (int st = 1; st < 1024; st <<= 1) {
        int v = (t >= st) ? sums[t - st] : 0;
        __syncthreads();
        sums[t] += v;
        __syncthreads();
    }
    int base = (t == 0) ? 0 : sums[t - 1];
    for (int i = b0; i < b1; i++) {
        off[i] = base;
        cur[i] = base;
        base += deg[i];
    }
    if (t == 1023) off[NN] = sums[1023];
}

__global__ void fill_kernel(const int* __restrict__ src, const int* __restrict__ dst,
                            int* __restrict__ cur, int* __restrict__ csrc)
{
    int e = blockIdx.x * blockDim.x + threadIdx.x;
    if (e >= EE) return;
    int d = dst[e];
    int pos = atomicAdd(&cur[d], 1);
    csrc[pos] = src[e];
}

// ---------------- fused node-centric attention ----------------
// one warp per node; pairwise unroll with pair-ahead prefetch (4 edges in flight).
// write_split: also emit bf16 hi/lo packed rows (feeds next layer's GEMM).
__global__ __launch_bounds__(256)
void attn_kernel(const float* __restrict__ q, const float* __restrict__ k,
                 const float* __restrict__ v, const float* __restrict__ skip,
                 const int* __restrict__ off, const int* __restrict__ csrc,
                 float* __restrict__ out,
                 unsigned* __restrict__ Ahi, unsigned* __restrict__ Alo,
                 int write_split)
{
    int node = (blockIdx.x * blockDim.x + threadIdx.x) >> 5;
    if (node >= NN) return;
    int lane = threadIdx.x & 31;

    const float4* qp = (const float4*)(q + (size_t)node * D1) + lane * 2;
    float4 qa = qp[0], qb = qp[1];
    const float4* sp = (const float4*)(skip + (size_t)node * D1) + lane * 2;
    float4 sa = sp[0], sb = sp[1];

    float n0 = 0.f, n1 = 0.f, n2 = 0.f, n3 = 0.f;
    float n4 = 0.f, n5 = 0.f, n6 = 0.f, n7 = 0.f;
    float den = 0.f;

    const int beg = off[node], end = off[node + 1];
    const int last = end - 1;

    if (beg < end) {
        // prologue: load first pair
        int s0 = csrc[beg];
        int s1 = csrc[(beg + 1 <= last) ? beg + 1 : last];
        const float4* kp0 = (const float4*)(k + (size_t)s0 * D1) + lane * 2;
        const float4* vp0 = (const float4*)(v + (size_t)s0 * D1) + lane * 2;
        const float4* kp1 = (const float4*)(k + (size_t)s1 * D1) + lane * 2;
        const float4* vp1 = (const float4*)(v + (size_t)s1 * D1) + lane * 2;
        float4 k0a = kp0[0], k0b = kp0[1], v0a = vp0[0], v0b = vp0[1];
        float4 k1a = kp1[0], k1b = kp1[1], v1a = vp1[0], v1b = vp1[1];

        for (int p = beg; p < end; p += 2) {
            // prefetch pair p+2 / p+3 (clamped; wasted loads at tail are harmless)
            int t0 = csrc[(p + 2 <= last) ? p + 2 : last];
            int t1 = csrc[(p + 3 <= last) ? p + 3 : last];
            const float4* kpa = (const float4*)(k + (size_t)t0 * D1) + lane * 2;
            const float4* vpa = (const float4*)(v + (size_t)t0 * D1) + lane * 2;
            const float4* kpb = (const float4*)(k + (size_t)t1 * D1) + lane * 2;
            const float4* vpb = (const float4*)(v + (size_t)t1 * D1) + lane * 2;
            float4 nk0a = kpa[0], nk0b = kpa[1], nv0a = vpa[0], nv0b = vpa[1];
            float4 nk1a = kpb[0], nk1b = kpb[1], nv1a = vpb[0], nv1b = vpb[1];

            // edge p
            {
                float d = qa.x * k0a.x + qa.y * k0a.y + qa.z * k0a.z + qa.w * k0a.w
                        + qb.x * k0b.x + qb.y * k0b.y + qb.z * k0b.z + qb.w * k0b.w;
                d += __shfl_xor_sync(0xffffffffu, d, 1);
                d += __shfl_xor_sync(0xffffffffu, d, 2);
                d += __shfl_xor_sync(0xffffffffu, d, 4);
                float ex = __expf(d * 0.125f);
                n0 += ex * v0a.x; n1 += ex * v0a.y; n2 += ex * v0a.z; n3 += ex * v0a.w;
                n4 += ex * v0b.x; n5 += ex * v0b.y; n6 += ex * v0b.z; n7 += ex * v0b.w;
                den += ex;
            }
            // edge p+1 (if it exists)
            if (p + 1 < end) {
                float d = qa.x * k1a.x + qa.y * k1a.y + qa.z * k1a.z + qa.w * k1a.w
                        + qb.x * k1b.x + qb.y * k1b.y + qb.z * k1b.z + qb.w * k1b.w;
                d += __shfl_xor_sync(0xffffffffu, d, 1);
                d += __shfl_xor_sync(0xffffffffu, d, 2);
                d += __shfl_xor_sync(0xffffffffu, d, 4);
                float ex = __expf(d * 0.125f);
                n0 += ex * v1a.x; n1 += ex * v1a.y; n2 += ex * v1a.z; n3 += ex * v1a.w;
                n4 += ex * v1b.x; n5 += ex * v1b.y; n6 += ex * v1b.z; n7 += ex * v1b.w;
                den += ex;
            }

            k0a = nk0a; k0b = nk0b; v0a = nv0a; v0b = nv0b;
            k1a = nk1a; k1b = nk1b; v1a = nv1a; v1b = nv1b;
        }
    }

    float inv = (end > beg) ? 1.f / den : 0.f;
    float4 oa, ob;
    oa.x = eluf(n0 * inv + sa.x);
    oa.y = eluf(n1 * inv + sa.y);
    oa.z = eluf(n2 * inv + sa.z);
    oa.w = eluf(n3 * inv + sa.w);
    ob.x = eluf(n4 * inv + sb.x);
    ob.y = eluf(n5 * inv + sb.y);
    ob.z = eluf(n6 * inv + sb.z);
    ob.w = eluf(n7 * inv + sb.w);
    float4* op = (float4*)(out + (size_t)node * D1) + lane * 2;
    op[0] = oa;
    op[1] = ob;

    if (write_split) {
        // packed bf16 hi/lo rows for next layer's GEMM (K-contiguous, 2 bf16/u32)
        uint4 hi4, lo4;
        split2(oa.x, oa.y, hi4.x, lo4.x);
        split2(oa.z, oa.w, hi4.y, lo4.y);
        split2(ob.x, ob.y, hi4.z, lo4.z);
        split2(ob.z, ob.w, hi4.w, lo4.w);
        size_t idx = (size_t)node * (D1 / 2) + lane * 4;
        *(uint4*)(Ahi + idx) = hi4;
        *(uint4*)(Alo + idx) = lo4;
    }
}

// ---------------- pooling ----------------
__global__ void zero_pool_kernel(float* pool, float* cnt)
{
    int i = blockIdx.x * blockDim.x + threadIdx.x;
    if (i < GG * D1) pool[i] = 0.f;
    if (i < GG) cnt[i] = 0.f;
}

__global__ void count_kernel(const int* __restrict__ batch, float* __restrict__ cnt)
{
    int n = blockIdx.x * blockDim.x + threadIdx.x;
    if (n < NN) atomicAdd(&cnt[batch[n]], 1.0f);
}

__global__ void pool_kernel(const float* __restrict__ h, const int* __restrict__ batch,
                            float* __restrict__ pool)
{
    int n0 = blockIdx.x * 64;
    if (n0 >= NN) return;
    int c = threadIdx.x;
    float acc = 0.f;
    int curg = batch[n0];
    for (int i = 0; i < 64; i++) {
        int n = n0 + i;
        if (n >= NN) break;
        int g = batch[n];
        if (g != curg) {
            atomicAdd(&pool[(size_t)curg * D1 + c], acc);
            acc = 0.f;
            curg = g;
        }
        acc += h[(size_t)n * D1 + c];
    }
    atomicAdd(&pool[(size_t)curg * D1 + c], acc);
}

// ---------------- classifier + log_softmax ----------------
__global__ void final_kernel(const float* __restrict__ pool, const float* __restrict__ cnt,
                             const float* __restrict__ Wl, const float* __restrict__ bl,
                             float* __restrict__ out)
{
    int g = blockIdx.x, t = threadIdx.x;
    __shared__ float red[256];
    __shared__ float logits[OUTC + 1];
    float invc = 1.0f / fmaxf(cnt[g], 1.0f);
    float p = pool[(size_t)g * D1 + t] * invc;
    for (int o = 0; o < OUTC; o++) {
        red[t] = p * Wl[t * OUTC + o];
        __syncthreads();
        for (int st = 128; st > 0; st >>= 1) {
            if (t < st) red[t] += red[t + st];
            __syncthreads();
        }
        if (t == 0) logits[o] = red[0] + bl[o];
        __syncthreads();
    }
    if (t == 0) {
        float m = -1e30f;
        for (int o = 0; o < OUTC; o++) m = fmaxf(m, logits[o]);
        float s = 0.f;
        for (int o = 0; o < OUTC; o++) s += expf(logits[o] - m);
        logits[OUTC] = m + logf(s);
    }
    __syncthreads();
    if (t < OUTC) out[g * OUTC + t] = logits[t] - logits[OUTC];
}

// ---------------- host-side orchestration ----------------
static void run_layer_mma(int K,
                          const float* Wq, const float* bq, const float* Wk, const float* bk,
                          const float* Wv, const float* bv, const float* Ws, const float* bs,
                          const int* off, const int* csrc,
                          unsigned* Ahi, unsigned* Alo, unsigned* Wthi, unsigned* Wtlo,
                          float* q, float* k, float* v, float* skip, float* hout,
                          int write_split)
{
    WPtrs wp; wp.W[0] = Wq; wp.W[1] = Wk; wp.W[2] = Wv; wp.W[3] = Ws;
    convW_kernel<<<dim3(D1 / 32, K / 32, 4), dim3(32, 8)>>>(wp, Wthi, Wtlo, K);

    TCOut pr;
    pr.bias[0] = bq; pr.bias[1] = bk; pr.bias[2] = bv; pr.bias[3] = bs;
    pr.C[0] = q;  pr.C[1] = k;  pr.C[2] = v;  pr.C[3] = skip;
    gemm_mma_kernel<<<dim3((NN + 127) / 128, 8), 256, SMEM_MMA>>>(
        Ahi, Alo, Wthi, Wtlo, pr, NN, K);

    attn_kernel<<<(NN * 32 + 255) / 256, 256>>>(q, k, v, skip, off, csrc, hout,
                                                Ahi, Alo, write_split);
}

extern "C" void kernel_launch(void* const* d_in, const int* in_sizes, int n_in,
                              void* d_out, int out_size)
{
    const float* x     = (const float*)d_in[0];
    const int*   ei    = (const int*)d_in[1];
    const int*   batch = (const int*)d_in[2];
    const float* Wq1 = (const float*)d_in[3],  *bq1 = (const float*)d_in[4];
    const float* Wk1 = (const float*)d_in[5],  *bk1 = (const float*)d_in[6];
    const float* Wv1 = (const float*)d_in[7],  *bv1 = (const float*)d_in[8];
    const float* Ws1 = (const float*)d_in[9],  *bs1 = (const float*)d_in[10];
    const float* Wq2 = (const float*)d_in[11], *bq2 = (const float*)d_in[12];
    const float* Wk2 = (const float*)d_in[13], *bk2 = (const float*)d_in[14];
    const float* Wv2 = (const float*)d_in[15], *bv2 = (const float*)d_in[16];
    const float* Ws2 = (const float*)d_in[17], *bs2 = (const float*)d_in[18];
    const float* Wl  = (const float*)d_in[19], *bl  = (const float*)d_in[20];
    float* out = (float*)d_out;

    const int* src = ei;
    const int* dst = ei + EE;

    float *q, *k, *v, *skip, *h, *pool, *cnt;
    int *deg, *off, *cur, *csrc;
    unsigned *Ahi, *Alo, *Wthi, *Wtlo;
    cudaGetSymbolAddress((void**)&q,    g_q);
    cudaGetSymbolAddress((void**)&k,    g_k);
    cudaGetSymbolAddress((void**)&v,    g_v);
    cudaGetSymbolAddress((void**)&skip, g_skip);
    cudaGetSymbolAddress((void**)&h,    g_h);
    cudaGetSymbolAddress((void**)&deg,  g_deg);
    cudaGetSymbolAddress((void**)&off,  g_off);
    cudaGetSymbolAddress((void**)&cur,  g_cur);
    cudaGetSymbolAddress((void**)&csrc, g_csrc);
    cudaGetSymbolAddress((void**)&pool, g_pool);
    cudaGetSymbolAddress((void**)&cnt,  g_cnt);
    cudaGetSymbolAddress((void**)&Ahi,  g_Ahi);
    cudaGetSymbolAddress((void**)&Alo,  g_Alo);
    cudaGetSymbolAddress((void**)&Wthi, g_Wthi);
    cudaGetSymbolAddress((void**)&Wtlo, g_Wtlo);

    // CSR build (shared by both layers)
    zero_deg_kernel<<<(NN + 255) / 256, 256>>>(deg);
    hist_kernel<<<(EE + 255) / 256, 256>>>(dst, deg);
    scan_kernel<<<1, 1024>>>(deg, off, cur);
    fill_kernel<<<(EE + 255) / 256, 256>>>(src, dst, cur, csrc);

    // layer 1: split x, GEMM, attn (attn emits split h for layer 2)
    {
        int n2 = NN * INC / 2;
        convA_kernel<<<(n2 + 255) / 256, 256>>>(x, Ahi, Alo, n2);
    }
    run_layer_mma(INC, Wq1, bq1, Wk1, bk1, Wv1, bv1, Ws1, bs1,
                  off, csrc, Ahi, Alo, Wthi, Wtlo, q, k, v, skip, h, 1);
    // layer 2: GEMM reads the split h emitted by layer-1 attn
    run_layer_mma(D1, Wq2, bq2, Wk2, bk2, Wv2, bv2, Ws2, bs2,
                  off, csrc, Ahi, Alo, Wthi, Wtlo, q, k, v, skip, h, 0);

    // mean pool per graph + classifier
    zero_pool_kernel<<<(GG * D1 + 255) / 256, 256>>>(pool, cnt);
    count_kernel<<<(NN + 255) / 256, 256>>>(batch, cnt);
    pool_kernel<<<(NN + 63) / 64, 256>>>(h, batch, pool);
    final_kernel<<<GG, 256>>>(pool, cnt, Wl, bl, out);
}

// round 13
// speedup vs baseline: 1.0125x; 1.0125x over previous
#include <cuda_runtime.h>
#include <cuda_bf16.h>
#include <math.h>

#define NN   50000
#define EE   400000
#define INC  128
#define D1   256
#define HH   4
#define HD   64
#define GG   64
#define OUTC 10

// ---------------- scratch (device globals; no allocation allowed) ----------------
__device__ float    g_q   [(size_t)NN * D1];
__device__ float    g_k   [(size_t)NN * D1];
__device__ float    g_v   [(size_t)NN * D1];
__device__ float    g_skip[(size_t)NN * D1];
__device__ float    g_h   [(size_t)NN * D1];
__device__ int      g_deg [NN];
__device__ int      g_off [NN + 1];
__device__ int      g_cur [NN];
__device__ int      g_csrc[EE];
__device__ float    g_pool[(size_t)GG * D1];
__device__ float    g_cnt [GG];
// bf16 hi/lo split operands (packed 2 x bf16 per u32, k-contiguous)
__device__ unsigned g_Ahi[(size_t)NN * D1 / 2];
__device__ unsigned g_Alo[(size_t)NN * D1 / 2];
__device__ unsigned g_Wthi[4 * D1 * D1 / 2];
__device__ unsigned g_Wtlo[4 * D1 * D1 / 2];

__device__ __forceinline__ float eluf(float x) { return x > 0.f ? x : expm1f(x); }

__device__ __forceinline__ void cp_async16(void* smem_dst, const void* gmem_src)
{
    unsigned saddr = (unsigned)__cvta_generic_to_shared(smem_dst);
    asm volatile("cp.async.cg.shared.global [%0], [%1], 16;"
                 :: "r"(saddr), "l"(gmem_src));
}
__device__ __forceinline__ void cp_async_commit() { asm volatile("cp.async.commit_group;"); }
__device__ __forceinline__ void cp_async_wait0()  { asm volatile("cp.async.wait_group 0;" ::: "memory"); }

// ---------------- mma.sync helpers (sm_80-era PTX; valid on compute_103) ---------
__device__ __forceinline__ void ldsm_x4(unsigned addr, unsigned* r)
{
    asm volatile("ldmatrix.sync.aligned.m8n8.x4.shared.b16 {%0,%1,%2,%3}, [%4];"
                 : "=r"(r[0]), "=r"(r[1]), "=r"(r[2]), "=r"(r[3]) : "r"(addr));
}
__device__ __forceinline__ void ldsm_x2(unsigned addr, unsigned* r)
{
    asm volatile("ldmatrix.sync.aligned.m8n8.x2.shared.b16 {%0,%1}, [%2];"
                 : "=r"(r[0]), "=r"(r[1]) : "r"(addr));
}
__device__ __forceinline__ void mma_bf16(float* c, const unsigned* a, const unsigned* b)
{
    asm volatile("mma.sync.aligned.m16n8k16.row.col.f32.bf16.bf16.f32 "
                 "{%0,%1,%2,%3}, {%4,%5,%6,%7}, {%8,%9}, {%0,%1,%2,%3};"
                 : "+f"(c[0]), "+f"(c[1]), "+f"(c[2]), "+f"(c[3])
                 : "r"(a[0]), "r"(a[1]), "r"(a[2]), "r"(a[3]),
                   "r"(b[0]), "r"(b[1]));
}

// ---------------- fp32 -> bf16 hi/lo split (packed pairs) ----------------
__device__ __forceinline__ unsigned pack_bf16(__nv_bfloat16 a, __nv_bfloat16 b)
{
    return (unsigned)__bfloat16_as_ushort(a) | ((unsigned)__bfloat16_as_ushort(b) << 16);
}
__device__ __forceinline__ void split2(float x, float y, unsigned& hi, unsigned& lo)
{
    __nv_bfloat16 hx = __float2bfloat16(x), hy = __float2bfloat16(y);
    __nv_bfloat16 lx = __float2bfloat16(x - __bfloat162float(hx));
    __nv_bfloat16 ly = __float2bfloat16(y - __bfloat162float(hy));
    hi = pack_bf16(hx, hy);
    lo = pack_bf16(lx, ly);
}

__global__ void convA_kernel(const float* __restrict__ X, unsigned* __restrict__ Ahi,
                             unsigned* __restrict__ Alo, int n2)
{
    int i = blockIdx.x * blockDim.x + threadIdx.x;
    if (i >= n2) return;
    float2 x = ((const float2*)X)[i];
    unsigned hi, lo;
    split2(x.x, x.y, hi, lo);
    Ahi[i] = hi;
    Alo[i] = lo;
}

struct WPtrs { const float* W[4]; };

// transpose W[K,256] -> Wt[256,K] (K-major rows) with hi/lo bf16 split
__global__ void convW_kernel(WPtrs wp, unsigned* __restrict__ Wthi,
                             unsigned* __restrict__ Wtlo, int K)
{
    __shared__ float t[32][33];
    int wi = blockIdx.z;
    const float* __restrict__ W = wp.W[wi];
    int n0 = blockIdx.x * 32, k0 = blockIdx.y * 32;
    for (int r = threadIdx.y; r < 32; r += 8)
        t[r][threadIdx.x] = W[(size_t)(k0 + r) * D1 + n0 + threadIdx.x];
    __syncthreads();
    int tid2 = threadIdx.y * 32 + threadIdx.x;
    int K2 = K >> 1;
    for (int i = tid2; i < 32 * 16; i += 256) {
        int n = i >> 4, kp = i & 15;
        unsigned hi, lo;
        split2(t[2 * kp][n], t[2 * kp + 1][n], hi, lo);
        size_t o = (size_t)(wi * D1 + n0 + n) * K2 + (k0 >> 1) + kp;
        Wthi[o] = hi;
        Wtlo[o] = lo;
    }
}

// ---------------- HMMA GEMM: C[wi][M,256] = A[M,K] @ W[wi][K,256] + b ------------
struct TCOut {
    const float* bias[4];
    float*       C[4];
};

#define ROWB   48
#define SECB   (128 * ROWB)      // 6144
#define CHUNKB (4 * SECB)        // 24576
#define SMEM_MMA (2 * CHUNKB)    // 49152

__global__ __launch_bounds__(256)
void gemm_mma_kernel(const unsigned* __restrict__ Ahi, const unsigned* __restrict__ Alo,
                     const unsigned* __restrict__ Wthi, const unsigned* __restrict__ Wtlo,
                     TCOut pr, int M, int K)
{
    extern __shared__ __align__(16) char smem[];
    const int tid = threadIdx.x, lane = tid & 31, wid = tid >> 5;
    const int bm = blockIdx.x, wi = blockIdx.y >> 1, bn = blockIdx.y & 1;
    const int warp_m = wid & 1, warp_n = wid >> 1;
    const int K2 = K >> 1, nkb = K >> 4;
    const unsigned sbase = (unsigned)__cvta_generic_to_shared(smem);

    const unsigned* gptr[4];
    unsigned sdst[4];
#pragma unroll
    for (int t = 0; t < 4; t++) {
        int id = tid + t * 256;
        int sec = id >> 8, sid = id & 255, row = sid >> 1, q = sid & 1;
        sdst[t] = sec * SECB + row * ROWB + q * 16;
        size_t rb;
        const unsigned* base;
        if (sec < 2) {
            int grow = bm * 128 + row;
            if (grow >= M) grow = M - 1;
            rb = (size_t)grow * K2;
            base = (sec == 0) ? Ahi : Alo;
        } else {
            int n = bn * 128 + row;
            rb = (size_t)(wi * D1 + n) * K2;
            base = (sec == 2) ? Wthi : Wtlo;
        }
        gptr[t] = base + rb + q * 4;
    }

    unsigned aAh[4], aAl[4], aBh[4], aBl[4];
#pragma unroll
    for (int i = 0; i < 4; i++) {
        unsigned arow = warp_m * 64 + i * 16 + (lane & 15);
        unsigned aoff = arow * ROWB + ((lane >> 4) << 4);
        aAh[i] = sbase + aoff;
        aAl[i] = sbase + SECB + aoff;
        unsigned brow = warp_n * 32 + i * 8 + (lane & 7);
        unsigned boff = brow * ROWB + (((lane >> 3) & 1) << 4);
        aBh[i] = sbase + 2 * SECB + boff;
        aBl[i] = sbase + 3 * SECB + boff;
    }

    float acc[4][4][4];
#pragma unroll
    for (int i = 0; i < 4; i++)
#pragma unroll
        for (int j = 0; j < 4; j++)
#pragma unroll
            for (int e = 0; e < 4; e++) acc[i][j][e] = 0.f;

#pragma unroll
    for (int t = 0; t < 4; t++) cp_async16(smem + sdst[t], gptr[t]);
    cp_async_commit();

    for (int kb = 0; kb < nkb; kb++) {
        const int cur = kb & 1;
        cp_async_wait0();
        __syncthreads();
        if (kb + 1 < nkb) {
            const unsigned bo = (cur ^ 1) * CHUNKB;
            const int go = (kb + 1) * 8;
#pragma unroll
            for (int t = 0; t < 4; t++)
                cp_async16(smem + bo + sdst[t], gptr[t] + go);
            cp_async_commit();
        }

        const unsigned bo = cur * CHUNKB;
        unsigned Ah[4][4], Al[4][4], Bh[4][2], Bl[4][2];
#pragma unroll
        for (int i = 0; i < 4; i++) {
            ldsm_x4(aAh[i] + bo, Ah[i]);
            ldsm_x4(aAl[i] + bo, Al[i]);
            ldsm_x2(aBh[i] + bo, Bh[i]);
            ldsm_x2(aBl[i] + bo, Bl[i]);
        }
#pragma unroll
        for (int i = 0; i < 4; i++)
#pragma unroll
            for (int j = 0; j < 4; j++) {
                mma_bf16(acc[i][j], Ah[i], Bh[j]);
                mma_bf16(acc[i][j], Ah[i], Bl[j]);
                mma_bf16(acc[i][j], Al[i], Bh[j]);
            }
        __syncthreads();
    }

    const float* __restrict__ bias = pr.bias[wi];
    float* __restrict__ C = pr.C[wi];
    const int colbase = bn * 128 + warp_n * 32;
#pragma unroll
    for (int j = 0; j < 4; j++) {
        int c0 = colbase + j * 8 + (lane & 3) * 2;
        float bx = bias[c0], by = bias[c0 + 1];
#pragma unroll
        for (int i = 0; i < 4; i++) {
            int r0 = bm * 128 + warp_m * 64 + i * 16 + (lane >> 2);
            if (r0 < M) {
                float2 o = make_float2(acc[i][j][0] + bx, acc[i][j][1] + by);
                *(float2*)(C + (size_t)r0 * D1 + c0) = o;
            }
            int r1 = r0 + 8;
            if (r1 < M) {
                float2 o = make_float2(acc[i][j][2] + bx, acc[i][j][3] + by);
                *(float2*)(C + (size_t)r1 * D1 + c0) = o;
            }
        }
    }
}

// ---------------- CSR build (by dst), once per launch ----------------
__global__ void zero_deg_kernel(int* deg)
{
    int i = blockIdx.x * blockDim.x + threadIdx.x;
    if (i < NN) deg[i] = 0;
}

__global__ void hist_kernel(const int* __restrict__ dst, int* __restrict__ deg)
{
    int e = blockIdx.x * blockDim.x + threadIdx.x;
    if (e < EE) atomicAdd(&deg[dst[e]], 1);
}

__global__ void scan_kernel(const int* __restrict__ deg, int* __restrict__ off,
                            int* __restrict__ cur)
{
    __shared__ int sums[1024];
    const int C = (NN + 1023) / 1024;
    int t = threadIdx.x;
    int b0 = t * C, b1 = min(b0 + C, NN);
    int s = 0;
    for (int i = b0; i < b1; i++) s += deg[i];
    sums[t] = s;
    __syncthreads();
    for (int st = 1; st < 1024; st <<= 1) {
        int v = (t >= st) ? sums[t - st] : 0;
        __syncthreads();
        sums[t] += v;
        __syncthreads();
    }
    int base = (t == 0) ? 0 : sums[t - 1];
    for (int i = b0; i < b1; i++) {
        off[i] = base;
        cur[i] = base;
        base += deg[i];
    }
    if (t == 1023) off[NN] = sums[1023];
}

__global__ void fill_kernel(const int* __restrict__ src, const int* __restrict__ dst,
                            int* __restrict__ cur, int* __restrict__ csrc)
{
    int e = blockIdx.x * blockDim.x + threadIdx.x;
    if (e >= EE) return;
    int d = dst[e];
    int pos = atomicAdd(&cur[d], 1);
    csrc[pos] = src[e];
}

// ---------------- fused node-centric attention: cp.async smem ring ----------------
// one warp per node; ring of AD slots (2KB each: k row + v row), prefetch
// distance AD-1 edges via cp.async.cg (no register cost, no wasted loads).
// Each lane reads back exactly the 32B it copied -> no cross-lane sync needed.
#define AD    6
#define SLOTB 2048
#define SMEM_ATTN (8 * AD * SLOTB)   // 96 KB per 256-thread CTA

__global__ __launch_bounds__(256)
void attn_kernel(const float* __restrict__ q, const float* __restrict__ k,
                 const float* __restrict__ v, const float* __restrict__ skip,
                 const int* __restrict__ off, const int* __restrict__ csrc,
                 float* __restrict__ out,
                 unsigned* __restrict__ Ahi, unsigned* __restrict__ Alo,
                 int write_split)
{
    extern __shared__ __align__(16) char asmem[];
    int node = (blockIdx.x * blockDim.x + threadIdx.x) >> 5;
    if (node >= NN) return;
    const int lane = threadIdx.x & 31;
    char* wbase = asmem + (threadIdx.x >> 5) * (AD * SLOTB);

    const float4* qp = (const float4*)(q + (size_t)node * D1) + lane * 2;
    float4 qa = qp[0], qb = qp[1];
    const float4* sp = (const float4*)(skip + (size_t)node * D1) + lane * 2;
    float4 sa = sp[0], sb = sp[1];

    float n0 = 0.f, n1 = 0.f, n2 = 0.f, n3 = 0.f;
    float n4 = 0.f, n5 = 0.f, n6 = 0.f, n7 = 0.f;
    float den = 0.f;

    const int beg = off[node], end = off[node + 1];
    int issued = beg;

    // prologue: prefetch up to AD-1 edges (one commit per slot, empty ok)
#pragma unroll
    for (int i = 0; i < AD - 1; i++) {
        if (issued < end) {
            int s = csrc[issued];
            char* slot = wbase + ((issued - beg) % AD) * SLOTB;
            const float* kr = k + (size_t)s * D1 + lane * 8;
            const float* vr = v + (size_t)s * D1 + lane * 8;
            cp_async16(slot + lane * 32,        kr);
            cp_async16(slot + lane * 32 + 16,   kr + 4);
            cp_async16(slot + 1024 + lane * 32,      vr);
            cp_async16(slot + 1024 + lane * 32 + 16, vr + 4);
            issued++;
        }
        cp_async_commit();
    }

    for (int p = beg; p < end; ++p) {
        asm volatile("cp.async.wait_group 4;" ::: "memory");   // AD-2
        char* slot = wbase + ((p - beg) % AD) * SLOTB;
        float4 ka = *(const float4*)(slot + lane * 32);
        float4 kb = *(const float4*)(slot + lane * 32 + 16);
        float4 va = *(const float4*)(slot + 1024 + lane * 32);
        float4 vb = *(const float4*)(slot + 1024 + lane * 32 + 16);

        // issue edge p+AD-1 into slot (p-beg-1)%AD (one-iteration-old slot)
        if (issued < end) {
            int s = csrc[issued];
            char* ns = wbase + ((issued - beg) % AD) * SLOTB;
            const float* kr = k + (size_t)s * D1 + lane * 8;
            const float* vr = v + (size_t)s * D1 + lane * 8;
            cp_async16(ns + lane * 32,        kr);
            cp_async16(ns + lane * 32 + 16,   kr + 4);
            cp_async16(ns + 1024 + lane * 32,      vr);
            cp_async16(ns + 1024 + lane * 32 + 16, vr + 4);
            issued++;
        }
        cp_async_commit();

        float d = qa.x * ka.x + qa.y * ka.y + qa.z * ka.z + qa.w * ka.w
                + qb.x * kb.x + qb.y * kb.y + qb.z * kb.z + qb.w * kb.w;
        d += __shfl_xor_sync(0xffffffffu, d, 1);
        d += __shfl_xor_sync(0xffffffffu, d, 2);
        d += __shfl_xor_sync(0xffffffffu, d, 4);
        float ex = __expf(d * 0.125f);   // 1/sqrt(64)
        n0 += ex * va.x; n1 += ex * va.y; n2 += ex * va.z; n3 += ex * va.w;
        n4 += ex * vb.x; n5 += ex * vb.y; n6 += ex * vb.z; n7 += ex * vb.w;
        den += ex;
    }

    float inv = (end > beg) ? 1.f / den : 0.f;
    float4 oa, ob;
    oa.x = eluf(n0 * inv + sa.x);
    oa.y = eluf(n1 * inv + sa.y);
    oa.z = eluf(n2 * inv + sa.z);
    oa.w = eluf(n3 * inv + sa.w);
    ob.x = eluf(n4 * inv + sb.x);
    ob.y = eluf(n5 * inv + sb.y);
    ob.z = eluf(n6 * inv + sb.z);
    ob.w = eluf(n7 * inv + sb.w);
    float4* op = (float4*)(out + (size_t)node * D1) + lane * 2;
    op[0] = oa;
    op[1] = ob;

    if (write_split) {
        uint4 hi4, lo4;
        split2(oa.x, oa.y, hi4.x, lo4.x);
        split2(oa.z, oa.w, hi4.y, lo4.y);
        split2(ob.x, ob.y, hi4.z, lo4.z);
        split2(ob.z, ob.w, hi4.w, lo4.w);
        size_t idx = (size_t)node * (D1 / 2) + lane * 4;
        *(uint4*)(Ahi + idx) = hi4;
        *(uint4*)(Alo + idx) = lo4;
    }
}

// ---------------- pooling ----------------
__global__ void zero_pool_kernel(float* pool, float* cnt)
{
    int i = blockIdx.x * blockDim.x + threadIdx.x;
    if (i < GG * D1) pool[i] = 0.f;
    if (i < GG) cnt[i] = 0.f;
}

__global__ void count_kernel(const int* __restrict__ batch, float* __restrict__ cnt)
{
    int n = blockIdx.x * blockDim.x + threadIdx.x;
    if (n < NN) atomicAdd(&cnt[batch[n]], 1.0f);
}

__global__ void pool_kernel(const float* __restrict__ h, const int* __restrict__ batch,
                            float* __restrict__ pool)
{
    int n0 = blockIdx.x * 64;
    if (n0 >= NN) return;
    int c = threadIdx.x;
    float acc = 0.f;
    int curg = batch[n0];
    for (int i = 0; i < 64; i++) {
        int n = n0 + i;
        if (n >= NN) break;
        int g = batch[n];
        if (g != curg) {
            atomicAdd(&pool[(size_t)curg * D1 + c], acc);
            acc = 0.f;
            curg = g;
        }
        acc += h[(size_t)n * D1 + c];
    }
    atomicAdd(&pool[(size_t)curg * D1 + c], acc);
}

// ---------------- classifier + log_softmax ----------------
__global__ void final_kernel(const float* __restrict__ pool, const float* __restrict__ cnt,
                             const float* __restrict__ Wl, const float* __restrict__ bl,
                             float* __restrict__ out)
{
    int g = blockIdx.x, t = threadIdx.x;
    __shared__ float red[256];
    __shared__ float logits[OUTC + 1];
    float invc = 1.0f / fmaxf(cnt[g], 1.0f);
    float p = pool[(size_t)g * D1 + t] * invc;
    for (int o = 0; o < OUTC; o++) {
        red[t] = p * Wl[t * OUTC + o];
        __syncthreads();
        for (int st = 128; st > 0; st >>= 1) {
            if (t < st) red[t] += red[t + st];
            __syncthreads();
        }
        if (t == 0) logits[o] = red[0] + bl[o];
        __syncthreads();
    }
    if (t == 0) {
        float m = -1e30f;
        for (int o = 0; o < OUTC; o++) m = fmaxf(m, logits[o]);
        float s = 0.f;
        for (int o = 0; o < OUTC; o++) s += expf(logits[o] - m);
        logits[OUTC] = m + logf(s);
    }
    __syncthreads();
    if (t < OUTC) out[g * OUTC + t] = logits[t] - logits[OUTC];
}

// ---------------- host-side orchestration ----------------
static void run_layer_mma(int K,
                          const float* Wq, const float* bq, const float* Wk, const float* bk,
                          const float* Wv, const float* bv, const float* Ws, const float* bs,
                          const int* off, const int* csrc,
                          unsigned* Ahi, unsigned* Alo, unsigned* Wthi, unsigned* Wtlo,
                          float* q, float* k, float* v, float* skip, float* hout,
                          int write_split)
{
    WPtrs wp; wp.W[0] = Wq; wp.W[1] = Wk; wp.W[2] = Wv; wp.W[3] = Ws;
    convW_kernel<<<dim3(D1 / 32, K / 32, 4), dim3(32, 8)>>>(wp, Wthi, Wtlo, K);

    TCOut pr;
    pr.bias[0] = bq; pr.bias[1] = bk; pr.bias[2] = bv; pr.bias[3] = bs;
    pr.C[0] = q;  pr.C[1] = k;  pr.C[2] = v;  pr.C[3] = skip;
    gemm_mma_kernel<<<dim3((NN + 127) / 128, 8), 256, SMEM_MMA>>>(
        Ahi, Alo, Wthi, Wtlo, pr, NN, K);

    attn_kernel<<<(NN * 32 + 255) / 256, 256, SMEM_ATTN>>>(q, k, v, skip, off, csrc,
                                                           hout, Ahi, Alo, write_split);
}

extern "C" void kernel_launch(void* const* d_in, const int* in_sizes, int n_in,
                              void* d_out, int out_size)
{
    const float* x     = (const float*)d_in[0];
    const int*   ei    = (const int*)d_in[1];
    const int*   batch = (const int*)d_in[2];
    const float* Wq1 = (const float*)d_in[3],  *bq1 = (const float*)d_in[4];
    const float* Wk1 = (const float*)d_in[5],  *bk1 = (const float*)d_in[6];
    const float* Wv1 = (const float*)d_in[7],  *bv1 = (const float*)d_in[8];
    const float* Ws1 = (const float*)d_in[9],  *bs1 = (const float*)d_in[10];
    const float* Wq2 = (const float*)d_in[11], *bq2 = (const float*)d_in[12];
    const float* Wk2 = (const float*)d_in[13], *bk2 = (const float*)d_in[14];
    const float* Wv2 = (const float*)d_in[15], *bv2 = (const float*)d_in[16];
    const float* Ws2 = (const float*)d_in[17], *bs2 = (const float*)d_in[18];
    const float* Wl  = (const float*)d_in[19], *bl  = (const float*)d_in[20];
    float* out = (float*)d_out;

    const int* src = ei;
    const int* dst = ei + EE;

    float *q, *k, *v, *skip, *h, *pool, *cnt;
    int *deg, *off, *cur, *csrc;
    unsigned *Ahi, *Alo, *Wthi, *Wtlo;
    cudaGetSymbolAddress((void**)&q,    g_q);
    cudaGetSymbolAddress((void**)&k,    g_k);
    cudaGetSymbolAddress((void**)&v,    g_v);
    cudaGetSymbolAddress((void**)&skip, g_skip);
    cudaGetSymbolAddress((void**)&h,    g_h);
    cudaGetSymbolAddress((void**)&deg,  g_deg);
    cudaGetSymbolAddress((void**)&off,  g_off);
    cudaGetSymbolAddress((void**)&cur,  g_cur);
    cudaGetSymbolAddress((void**)&csrc, g_csrc);
    cudaGetSymbolAddress((void**)&pool, g_pool);
    cudaGetSymbolAddress((void**)&cnt,  g_cnt);
    cudaGetSymbolAddress((void**)&Ahi,  g_Ahi);
    cudaGetSymbolAddress((void**)&Alo,  g_Alo);
    cudaGetSymbolAddress((void**)&Wthi, g_Wthi);
    cudaGetSymbolAddress((void**)&Wtlo, g_Wtlo);

    // attn kernel needs 96KB dynamic smem
    cudaFuncSetAttribute(attn_kernel,
                         cudaFuncAttributeMaxDynamicSharedMemorySize, SMEM_ATTN);

    // CSR build (shared by both layers)
    zero_deg_kernel<<<(NN + 255) / 256, 256>>>(deg);
    hist_kernel<<<(EE + 255) / 256, 256>>>(dst, deg);
    scan_kernel<<<1, 1024>>>(deg, off, cur);
    fill_kernel<<<(EE + 255) / 256, 256>>>(src, dst, cur, csrc);

    // layer 1: split x, GEMM, attn (attn emits split h for layer 2)
    {
        int n2 = NN * INC / 2;
        convA_kernel<<<(n2 + 255) / 256, 256>>>(x, Ahi, Alo, n2);
    }
    run_layer_mma(INC, Wq1, bq1, Wk1, bk1, Wv1, bv1, Ws1, bs1,
                  off, csrc, Ahi, Alo, Wthi, Wtlo, q, k, v, skip, h, 1);
    // layer 2: GEMM reads the split h emitted by layer-1 attn
    run_layer_mma(D1, Wq2, bq2, Wk2, bk2, Wv2, bv2, Ws2, bs2,
                  off, csrc, Ahi, Alo, Wthi, Wtlo, q, k, v, skip, h, 0);

    // mean pool per graph + classifier
    zero_pool_kernel<<<(GG * D1 + 255) / 256, 256>>>(pool, cnt);
    count_kernel<<<(NN + 255) / 256, 256>>>(batch, cnt);
    pool_kernel<<<(NN + 63) / 64, 256>>>(h, batch, pool);
    final_kernel<<<GG, 256>>>(pool, cnt, Wl, bl, out);
}

// round 15
// speedup vs baseline: 1.1712x; 1.1567x over previous
#include <cuda_runtime.h>
#include <cuda_bf16.h>
#include <math.h>

#define NN   50000
#define EE   400000
#define INC  128
#define D1   256
#define HH   4
#define HD   64
#define GG   64
#define OUTC 10

// ---------------- scratch (device globals; no allocation allowed) ----------------
__device__ float    g_q   [(size_t)NN * D1];
__device__ float    g_skip[(size_t)NN * D1];
__device__ float    g_h   [(size_t)NN * D1];
__device__ unsigned g_kbf [(size_t)NN * D1 / 2];   // k rows, packed bf16 pairs
__device__ unsigned g_vbf [(size_t)NN * D1 / 2];   // v rows, packed bf16 pairs
__device__ int      g_deg [NN];
__device__ int      g_off [NN + 1];
__device__ int      g_cur [NN];
__device__ int      g_csrc[EE];
__device__ float    g_pool[(size_t)GG * D1];
__device__ float    g_cnt [GG];
// bf16 hi/lo split operands (packed 2 x bf16 per u32, k-contiguous)
__device__ unsigned g_Ahi[(size_t)NN * D1 / 2];
__device__ unsigned g_Alo[(size_t)NN * D1 / 2];
__device__ unsigned g_Wthi[4 * D1 * D1 / 2];
__device__ unsigned g_Wtlo[4 * D1 * D1 / 2];

__device__ __forceinline__ float eluf(float x) { return x > 0.f ? x : expm1f(x); }

__device__ __forceinline__ void cp_async16(void* smem_dst, const void* gmem_src)
{
    unsigned saddr = (unsigned)__cvta_generic_to_shared(smem_dst);
    asm volatile("cp.async.cg.shared.global [%0], [%1], 16;"
                 :: "r"(saddr), "l"(gmem_src));
}
__device__ __forceinline__ void cp_async_commit() { asm volatile("cp.async.commit_group;"); }
__device__ __forceinline__ void cp_async_wait0()  { asm volatile("cp.async.wait_group 0;" ::: "memory"); }

// ---------------- mma.sync helpers (sm_80-era PTX; valid on compute_103) ---------
__device__ __forceinline__ void ldsm_x4(unsigned addr, unsigned* r)
{
    asm volatile("ldmatrix.sync.aligned.m8n8.x4.shared.b16 {%0,%1,%2,%3}, [%4];"
                 : "=r"(r[0]), "=r"(r[1]), "=r"(r[2]), "=r"(r[3]) : "r"(addr));
}
__device__ __forceinline__ void ldsm_x2(unsigned addr, unsigned* r)
{
    asm volatile("ldmatrix.sync.aligned.m8n8.x2.shared.b16 {%0,%1}, [%2];"
                 : "=r"(r[0]), "=r"(r[1]) : "r"(addr));
}
__device__ __forceinline__ void mma_bf16(float* c, const unsigned* a, const unsigned* b)
{
    asm volatile("mma.sync.aligned.m16n8k16.row.col.f32.bf16.bf16.f32 "
                 "{%0,%1,%2,%3}, {%4,%5,%6,%7}, {%8,%9}, {%0,%1,%2,%3};"
                 : "+f"(c[0]), "+f"(c[1]), "+f"(c[2]), "+f"(c[3])
                 : "r"(a[0]), "r"(a[1]), "r"(a[2]), "r"(a[3]),
                   "r"(b[0]), "r"(b[1]));
}

// ---------------- bf16 pack/unpack helpers ----------------
__device__ __forceinline__ unsigned pack_bf16(__nv_bfloat16 a, __nv_bfloat16 b)
{
    return (unsigned)__bfloat16_as_ushort(a) | ((unsigned)__bfloat16_as_ushort(b) << 16);
}
__device__ __forceinline__ void split2(float x, float y, unsigned& hi, unsigned& lo)
{
    __nv_bfloat16 hx = __float2bfloat16(x), hy = __float2bfloat16(y);
    __nv_bfloat16 lx = __float2bfloat16(x - __bfloat162float(hx));
    __nv_bfloat16 ly = __float2bfloat16(y - __bfloat162float(hy));
    hi = pack_bf16(hx, hy);
    lo = pack_bf16(lx, ly);
}
__device__ __forceinline__ float2 bf2f(unsigned u)
{
    __nv_bfloat162 b = *reinterpret_cast<__nv_bfloat162*>(&u);
    return __bfloat1622float2(b);
}

__global__ void convA_kernel(const float* __restrict__ X, unsigned* __restrict__ Ahi,
                             unsigned* __restrict__ Alo, int n2)
{
    int i = blockIdx.x * blockDim.x + threadIdx.x;
    if (i >= n2) return;
    float2 x = ((const float2*)X)[i];
    unsigned hi, lo;
    split2(x.x, x.y, hi, lo);
    Ahi[i] = hi;
    Alo[i] = lo;
}

struct WPtrs { const float* W[4]; };

// transpose W[K,256] -> Wt[256,K] (K-major rows) with hi/lo bf16 split
__global__ void convW_kernel(WPtrs wp, unsigned* __restrict__ Wthi,
                             unsigned* __restrict__ Wtlo, int K)
{
    __shared__ float t[32][33];
    int wi = blockIdx.z;
    const float* __restrict__ W = wp.W[wi];
    int n0 = blockIdx.x * 32, k0 = blockIdx.y * 32;
    for (int r = threadIdx.y; r < 32; r += 8)
        t[r][threadIdx.x] = W[(size_t)(k0 + r) * D1 + n0 + threadIdx.x];
    __syncthreads();
    int tid2 = threadIdx.y * 32 + threadIdx.x;
    int K2 = K >> 1;
    for (int i = tid2; i < 32 * 16; i += 256) {
        int n = i >> 4, kp = i & 15;
        unsigned hi, lo;
        split2(t[2 * kp][n], t[2 * kp + 1][n], hi, lo);
        size_t o = (size_t)(wi * D1 + n0 + n) * K2 + (k0 >> 1) + kp;
        Wthi[o] = hi;
        Wtlo[o] = lo;
    }
}

// ---------------- HMMA GEMM: C[wi][M,256] = A[M,K] @ W[wi][K,256] + b ------------
// Outputs: fp32 (q, skip) or packed-bf16 rows (k, v) when Cb[wi] != nullptr.
struct TCOut {
    const float* bias[4];
    float*       C[4];
    unsigned*    Cb[4];
};

#define ROWB   48
#define SECB   (128 * ROWB)      // 6144
#define CHUNKB (4 * SECB)        // 24576
#define SMEM_MMA (2 * CHUNKB)    // 49152

__global__ __launch_bounds__(256)
void gemm_mma_kernel(const unsigned* __restrict__ Ahi, const unsigned* __restrict__ Alo,
                     const unsigned* __restrict__ Wthi, const unsigned* __restrict__ Wtlo,
                     TCOut pr, int M, int K)
{
    extern __shared__ __align__(16) char smem[];
    const int tid = threadIdx.x, lane = tid & 31, wid = tid >> 5;
    const int bm = blockIdx.x, wi = blockIdx.y >> 1, bn = blockIdx.y & 1;
    const int warp_m = wid & 1, warp_n = wid >> 1;
    const int K2 = K >> 1, nkb = K >> 4;
    const unsigned sbase = (unsigned)__cvta_generic_to_shared(smem);

    const unsigned* gptr[4];
    unsigned sdst[4];
#pragma unroll
    for (int t = 0; t < 4; t++) {
        int id = tid + t * 256;
        int sec = id >> 8, sid = id & 255, row = sid >> 1, q = sid & 1;
        sdst[t] = sec * SECB + row * ROWB + q * 16;
        size_t rb;
        const unsigned* base;
        if (sec < 2) {
            int grow = bm * 128 + row;
            if (grow >= M) grow = M - 1;
            rb = (size_t)grow * K2;
            base = (sec == 0) ? Ahi : Alo;
        } else {
            int n = bn * 128 + row;
            rb = (size_t)(wi * D1 + n) * K2;
            base = (sec == 2) ? Wthi : Wtlo;
        }
        gptr[t] = base + rb + q * 4;
    }

    unsigned aAh[4], aAl[4], aBh[4], aBl[4];
#pragma unroll
    for (int i = 0; i < 4; i++) {
        unsigned arow = warp_m * 64 + i * 16 + (lane & 15);
        unsigned aoff = arow * ROWB + ((lane >> 4) << 4);
        aAh[i] = sbase + aoff;
        aAl[i] = sbase + SECB + aoff;
        unsigned brow = warp_n * 32 + i * 8 + (lane & 7);
        unsigned boff = brow * ROWB + (((lane >> 3) & 1) << 4);
        aBh[i] = sbase + 2 * SECB + boff;
        aBl[i] = sbase + 3 * SECB + boff;
    }

    float acc[4][4][4];
#pragma unroll
    for (int i = 0; i < 4; i++)
#pragma unroll
        for (int j = 0; j < 4; j++)
#pragma unroll
            for (int e = 0; e < 4; e++) acc[i][j][e] = 0.f;

#pragma unroll
    for (int t = 0; t < 4; t++) cp_async16(smem + sdst[t], gptr[t]);
    cp_async_commit();

    for (int kb = 0; kb < nkb; kb++) {
        const int cur = kb & 1;
        cp_async_wait0();
        __syncthreads();
        if (kb + 1 < nkb) {
            const unsigned bo = (cur ^ 1) * CHUNKB;
            const int go = (kb + 1) * 8;
#pragma unroll
            for (int t = 0; t < 4; t++)
                cp_async16(smem + bo + sdst[t], gptr[t] + go);
            cp_async_commit();
        }

        const unsigned bo = cur * CHUNKB;
        unsigned Ah[4][4], Al[4][4], Bh[4][2], Bl[4][2];
#pragma unroll
        for (int i = 0; i < 4; i++) {
            ldsm_x4(aAh[i] + bo, Ah[i]);
            ldsm_x4(aAl[i] + bo, Al[i]);
            ldsm_x2(aBh[i] + bo, Bh[i]);
            ldsm_x2(aBl[i] + bo, Bl[i]);
        }
#pragma unroll
        for (int i = 0; i < 4; i++)
#pragma unroll
            for (int j = 0; j < 4; j++) {
                mma_bf16(acc[i][j], Ah[i], Bh[j]);
                mma_bf16(acc[i][j], Ah[i], Bl[j]);
                mma_bf16(acc[i][j], Al[i], Bh[j]);
            }
        __syncthreads();
    }

    const float* __restrict__ bias = pr.bias[wi];
    const int colbase = bn * 128 + warp_n * 32;
    unsigned* __restrict__ Cb = pr.Cb[wi];
    if (Cb) {
        // bf16 packed output (k / v)
#pragma unroll
        for (int j = 0; j < 4; j++) {
            int c0 = colbase + j * 8 + (lane & 3) * 2;
            float bx = bias[c0], by = bias[c0 + 1];
#pragma unroll
            for (int i = 0; i < 4; i++) {
                int r0 = bm * 128 + warp_m * 64 + i * 16 + (lane >> 2);
                if (r0 < M)
                    Cb[(size_t)r0 * (D1 / 2) + (c0 >> 1)] =
                        pack_bf16(__float2bfloat16(acc[i][j][0] + bx),
                                  __float2bfloat16(acc[i][j][1] + by));
                int r1 = r0 + 8;
                if (r1 < M)
                    Cb[(size_t)r1 * (D1 / 2) + (c0 >> 1)] =
                        pack_bf16(__float2bfloat16(acc[i][j][2] + bx),
                                  __float2bfloat16(acc[i][j][3] + by));
            }
        }
    } else {
        float* __restrict__ C = pr.C[wi];
#pragma unroll
        for (int j = 0; j < 4; j++) {
            int c0 = colbase + j * 8 + (lane & 3) * 2;
            float bx = bias[c0], by = bias[c0 + 1];
#pragma unroll
            for (int i = 0; i < 4; i++) {
                int r0 = bm * 128 + warp_m * 64 + i * 16 + (lane >> 2);
                if (r0 < M) {
                    float2 o = make_float2(acc[i][j][0] + bx, acc[i][j][1] + by);
                    *(float2*)(C + (size_t)r0 * D1 + c0) = o;
                }
                int r1 = r0 + 8;
                if (r1 < M) {
                    float2 o = make_float2(acc[i][j][2] + bx, acc[i][j][3] + by);
                    *(float2*)(C + (size_t)r1 * D1 + c0) = o;
                }
            }
        }
    }
}

// ---------------- CSR build (by dst), once per launch ----------------
__global__ void zero_deg_kernel(int* deg)
{
    int i = blockIdx.x * blockDim.x + threadIdx.x;
    if (i < NN) deg[i] = 0;
}

__global__ void hist_kernel(const int* __restrict__ dst, int* __restrict__ deg)
{
    int e = blockIdx.x * blockDim.x + threadIdx.x;
    if (e < EE) atomicAdd(&deg[dst[e]], 1);
}

__global__ void scan_kernel(const int* __restrict__ deg, int* __restrict__ off,
                            int* __restrict__ cur)
{
    __shared__ int sums[1024];
    const int C = (NN + 1023) / 1024;
    int t = threadIdx.x;
    int b0 = t * C, b1 = min(b0 + C, NN);
    int s = 0;
    for (int i = b0; i < b1; i++) s += deg[i];
    sums[t] = s;
    __syncthreads();
    for (int st = 1; st < 1024; st <<= 1) {
        int v = (t >= st) ? sums[t - st] : 0;
        __syncthreads();
        sums[t] += v;
        __syncthreads();
    }
    int base = (t == 0) ? 0 : sums[t - 1];
    for (int i = b0; i < b1; i++) {
        off[i] = base;
        cur[i] = base;
        base += deg[i];
    }
    if (t == 1023) off[NN] = sums[1023];
}

__global__ void fill_kernel(const int* __restrict__ src, const int* __restrict__ dst,
                            int* __restrict__ cur, int* __restrict__ csrc)
{
    int e = blockIdx.x * blockDim.x + threadIdx.x;
    if (e >= EE) return;
    int d = dst[e];
    int pos = atomicAdd(&cur[d], 1);
    csrc[pos] = src[e];
}

// ---------------- fused node-centric attention (bf16 k/v gathers) ----------------
// one warp per node; 2-deep register prefetch (proven R10 structure).
// k/v rows are packed bf16: 512B/row, 1 uint4 per lane per row.
__global__ __launch_bounds__(256)
void attn_kernel(const float* __restrict__ q, const unsigned* __restrict__ kbf,
                 const unsigned* __restrict__ vbf, const float* __restrict__ skip,
                 const int* __restrict__ off, const int* __restrict__ csrc,
                 float* __restrict__ out,
                 unsigned* __restrict__ Ahi, unsigned* __restrict__ Alo,
                 int write_split)
{
    int node = (blockIdx.x * blockDim.x + threadIdx.x) >> 5;
    if (node >= NN) return;
    int lane = threadIdx.x & 31;

    const float4* qp = (const float4*)(q + (size_t)node * D1) + lane * 2;
    float4 qa = qp[0], qb = qp[1];
    const float4* sp = (const float4*)(skip + (size_t)node * D1) + lane * 2;
    float4 sa = sp[0], sb = sp[1];

    float n0 = 0.f, n1 = 0.f, n2 = 0.f, n3 = 0.f;
    float n4 = 0.f, n5 = 0.f, n6 = 0.f, n7 = 0.f;
    float den = 0.f;

    const int beg = off[node], end = off[node + 1];
    const int last = end - 1;

    uint4 kw, vw;
    if (beg < end) {
        int s = csrc[beg];
        kw = *((const uint4*)(kbf + (size_t)s * (D1 / 2)) + lane);
        vw = *((const uint4*)(vbf + (size_t)s * (D1 / 2)) + lane);
    }

    for (int p = beg; p < end; ++p) {
        // prefetch next edge's rows while computing this one
        int pn = (p + 1 < end) ? (p + 1) : last;
        int s2 = csrc[pn];
        uint4 kw2 = *((const uint4*)(kbf + (size_t)s2 * (D1 / 2)) + lane);
        uint4 vw2 = *((const uint4*)(vbf + (size_t)s2 * (D1 / 2)) + lane);

        float2 k0 = bf2f(kw.x), k1 = bf2f(kw.y), k2 = bf2f(kw.z), k3 = bf2f(kw.w);
        float d = qa.x * k0.x + qa.y * k0.y + qa.z * k1.x + qa.w * k1.y
                + qb.x * k2.x + qb.y * k2.y + qb.z * k3.x + qb.w * k3.y;
        d += __shfl_xor_sync(0xffffffffu, d, 1);
        d += __shfl_xor_sync(0xffffffffu, d, 2);
        d += __shfl_xor_sync(0xffffffffu, d, 4);
        float ex = __expf(d * 0.125f);   // 1/sqrt(64)
        float2 v0 = bf2f(vw.x), v1 = bf2f(vw.y), v2 = bf2f(vw.z), v3 = bf2f(vw.w);
        n0 += ex * v0.x; n1 += ex * v0.y; n2 += ex * v1.x; n3 += ex * v1.y;
        n4 += ex * v2.x; n5 += ex * v2.y; n6 += ex * v3.x; n7 += ex * v3.y;
        den += ex;

        kw = kw2; vw = vw2;
    }

    float inv = (end > beg) ? 1.f / den : 0.f;
    float4 oa, ob;
    oa.x = eluf(n0 * inv + sa.x);
    oa.y = eluf(n1 * inv + sa.y);
    oa.z = eluf(n2 * inv + sa.z);
    oa.w = eluf(n3 * inv + sa.w);
    ob.x = eluf(n4 * inv + sb.x);
    ob.y = eluf(n5 * inv + sb.y);
    ob.z = eluf(n6 * inv + sb.z);
    ob.w = eluf(n7 * inv + sb.w);
    float4* op = (float4*)(out + (size_t)node * D1) + lane * 2;
    op[0] = oa;
    op[1] = ob;

    if (write_split) {
        // packed bf16 hi/lo rows for next layer's GEMM (K-contiguous, 2 bf16/u32)
        uint4 hi4, lo4;
        split2(oa.x, oa.y, hi4.x, lo4.x);
        split2(oa.z, oa.w, hi4.y, lo4.y);
        split2(ob.x, ob.y, hi4.z, lo4.z);
        split2(ob.z, ob.w, hi4.w, lo4.w);
        size_t idx = (size_t)node * (D1 / 2) + lane * 4;
        *(uint4*)(Ahi + idx) = hi4;
        *(uint4*)(Alo + idx) = lo4;
    }
}

// ---------------- pooling ----------------
__global__ void zero_pool_kernel(float* pool, float* cnt)
{
    int i = blockIdx.x * blockDim.x + threadIdx.x;
    if (i < GG * D1) pool[i] = 0.f;
    if (i < GG) cnt[i] = 0.f;
}

__global__ void count_kernel(const int* __restrict__ batch, float* __restrict__ cnt)
{
    int n = blockIdx.x * blockDim.x + threadIdx.x;
    if (n < NN) atomicAdd(&cnt[batch[n]], 1.0f);
}

__global__ void pool_kernel(const float* __restrict__ h, const int* __restrict__ batch,
                            float* __restrict__ pool)
{
    int n0 = blockIdx.x * 64;
    if (n0 >= NN) return;
    int c = threadIdx.x;
    float acc = 0.f;
    int curg = batch[n0];
    for (int i = 0; i < 64; i++) {
        int n = n0 + i;
        if (n >= NN) break;
        int g = batch[n];
        if (g != curg) {
            atomicAdd(&pool[(size_t)curg * D1 + c], acc);
            acc = 0.f;
            curg = g;
        }
        acc += h[(size_t)n * D1 + c];
    }
    atomicAdd(&pool[(size_t)curg * D1 + c], acc);
}

// ---------------- classifier + log_softmax ----------------
__global__ void final_kernel(const float* __restrict__ pool, const float* __restrict__ cnt,
                             const float* __restrict__ Wl, const float* __restrict__ bl,
                             float* __restrict__ out)
{
    int g = blockIdx.x, t = threadIdx.x;
    __shared__ float red[256];
    __shared__ float logits[OUTC + 1];
    float invc = 1.0f / fmaxf(cnt[g], 1.0f);
    float p = pool[(size_t)g * D1 + t] * invc;
    for (int o = 0; o < OUTC; o++) {
        red[t] = p * Wl[t * OUTC + o];
        __syncthreads();
        for (int st = 128; st > 0; st >>= 1) {
            if (t < st) red[t] += red[t + st];
            __syncthreads();
        }
        if (t == 0) logits[o] = red[0] + bl[o];
        __syncthreads();
    }
    if (t == 0) {
        float m = -1e30f;
        for (int o = 0; o < OUTC; o++) m = fmaxf(m, logits[o]);
        float s = 0.f;
        for (int o = 0; o < OUTC; o++) s += expf(logits[o] - m);
        logits[OUTC] = m + logf(s);
    }
    __syncthreads();
    if (t < OUTC) out[g * OUTC + t] = logits[t] - logits[OUTC];
}

// ---------------- host-side orchestration ----------------
static void run_layer_mma(int K,
                          const float* Wq, const float* bq, const float* Wk, const float* bk,
                          const float* Wv, const float* bv, const float* Ws, const float* bs,
                          const int* off, const int* csrc,
                          unsigned* Ahi, unsigned* Alo, unsigned* Wthi, unsigned* Wtlo,
                          float* q, unsigned* kbf, unsigned* vbf, float* skip, float* hout,
                          int write_split)
{
    WPtrs wp; wp.W[0] = Wq; wp.W[1] = Wk; wp.W[2] = Wv; wp.W[3] = Ws;
    convW_kernel<<<dim3(D1 / 32, K / 32, 4), dim3(32, 8)>>>(wp, Wthi, Wtlo, K);

    TCOut pr;
    pr.bias[0] = bq; pr.bias[1] = bk; pr.bias[2] = bv; pr.bias[3] = bs;
    pr.C[0] = q;      pr.C[1] = nullptr; pr.C[2] = nullptr; pr.C[3] = skip;
    pr.Cb[0] = nullptr; pr.Cb[1] = kbf;  pr.Cb[2] = vbf;    pr.Cb[3] = nullptr;
    gemm_mma_kernel<<<dim3((NN + 127) / 128, 8), 256, SMEM_MMA>>>(
        Ahi, Alo, Wthi, Wtlo, pr, NN, K);

    attn_kernel<<<(NN * 32 + 255) / 256, 256>>>(q, kbf, vbf, skip, off, csrc,
                                                hout, Ahi, Alo, write_split);
}

extern "C" void kernel_launch(void* const* d_in, const int* in_sizes, int n_in,
                              void* d_out, int out_size)
{
    const float* x     = (const float*)d_in[0];
    const int*   ei    = (const int*)d_in[1];
    const int*   batch = (const int*)d_in[2];
    const float* Wq1 = (const float*)d_in[3],  *bq1 = (const float*)d_in[4];
    const float* Wk1 = (const float*)d_in[5],  *bk1 = (const float*)d_in[6];
    const float* Wv1 = (const float*)d_in[7],  *bv1 = (const float*)d_in[8];
    const float* Ws1 = (const float*)d_in[9],  *bs1 = (const float*)d_in[10];
    const float* Wq2 = (const float*)d_in[11], *bq2 = (const float*)d_in[12];
    const float* Wk2 = (const float*)d_in[13], *bk2 = (const float*)d_in[14];
    const float* Wv2 = (const float*)d_in[15], *bv2 = (const float*)d_in[16];
    const float* Ws2 = (const float*)d_in[17], *bs2 = (const float*)d_in[18];
    const float* Wl  = (const float*)d_in[19], *bl  = (const float*)d_in[20];
    float* out = (float*)d_out;

    const int* src = ei;
    const int* dst = ei + EE;

    float *q, *skip, *h, *pool, *cnt;
    int *deg, *off, *cur, *csrc;
    unsigned *kbf, *vbf, *Ahi, *Alo, *Wthi, *Wtlo;
    cudaGetSymbolAddress((void**)&q,    g_q);
    cudaGetSymbolAddress((void**)&skip, g_skip);
    cudaGetSymbolAddress((void**)&h,    g_h);
    cudaGetSymbolAddress((void**)&kbf,  g_kbf);
    cudaGetSymbolAddress((void**)&vbf,  g_vbf);
    cudaGetSymbolAddress((void**)&deg,  g_deg);
    cudaGetSymbolAddress((void**)&off,  g_off);
    cudaGetSymbolAddress((void**)&cur,  g_cur);
    cudaGetSymbolAddress((void**)&csrc, g_csrc);
    cudaGetSymbolAddress((void**)&pool, g_pool);
    cudaGetSymbolAddress((void**)&cnt,  g_cnt);
    cudaGetSymbolAddress((void**)&Ahi,  g_Ahi);
    cudaGetSymbolAddress((void**)&Alo,  g_Alo);
    cudaGetSymbolAddress((void**)&Wthi, g_Wthi);
    cudaGetSymbolAddress((void**)&Wtlo, g_Wtlo);

    // CSR build (shared by both layers)
    zero_deg_kernel<<<(NN + 255) / 256, 256>>>(deg);
    hist_kernel<<<(EE + 255) / 256, 256>>>(dst, deg);
    scan_kernel<<<1, 1024>>>(deg, off, cur);
    fill_kernel<<<(EE + 255) / 256, 256>>>(src, dst, cur, csrc);

    // layer 1: split x, GEMM, attn (attn emits split h for layer 2)
    {
        int n2 = NN * INC / 2;
        convA_kernel<<<(n2 + 255) / 256, 256>>>(x, Ahi, Alo, n2);
    }
    run_layer_mma(INC, Wq1, bq1, Wk1, bk1, Wv1, bv1, Ws1, bs1,
                  off, csrc, Ahi, Alo, Wthi, Wtlo, q, kbf, vbf, skip, h, 1);
    // layer 2: GEMM reads the split h emitted by layer-1 attn
    run_layer_mma(D1, Wq2, bq2, Wk2, bk2, Wv2, bv2, Ws2, bs2,
                  off, csrc, Ahi, Alo, Wthi, Wtlo, q, kbf, vbf, skip, h, 0);

    // mean pool per graph + classifier
    zero_pool_kernel<<<(GG * D1 + 255) / 256, 256>>>(pool, cnt);
    count_kernel<<<(NN + 255) / 256, 256>>>(batch, cnt);
    pool_kernel<<<(NN + 63) / 64, 256>>>(h, batch, pool);
    final_kernel<<<GG, 256>>>(pool, cnt, Wl, bl, out);
}

// round 16
// speedup vs baseline: 1.5868x; 1.3549x over previous
#include <cuda_runtime.h>
#include <cuda_bf16.h>
#include <math.h>

#define NN   50000
#define EE   400000
#define INC  128
#define D1   256
#define HH   4
#define HD   64
#define GG   64
#define OUTC 10

// ---------------- scratch (device globals; no allocation allowed) ----------------
__device__ float    g_q   [(size_t)NN * D1];
__device__ float    g_skip[(size_t)NN * D1];
__device__ float    g_h   [(size_t)NN * D1];
__device__ unsigned g_kvbf[(size_t)NN * D1];       // interleaved: k row (128 u32) | v row (128 u32)
__device__ int      g_deg [NN];
__device__ int      g_off [NN + 1];
__device__ int      g_cur [NN];
__device__ int      g_csrc[EE];
__device__ float    g_pool[(size_t)GG * D1];
__device__ float    g_cnt [GG];
// bf16 operands (packed 2 x bf16 per u32, k-contiguous)
__device__ unsigned g_Abf[(size_t)NN * D1 / 2];
__device__ unsigned g_Wtbf[4 * D1 * D1 / 2];

__device__ __forceinline__ float eluf(float x) { return x > 0.f ? x : expm1f(x); }

__device__ __forceinline__ void cp_async16(void* smem_dst, const void* gmem_src)
{
    unsigned saddr = (unsigned)__cvta_generic_to_shared(smem_dst);
    asm volatile("cp.async.cg.shared.global [%0], [%1], 16;"
                 :: "r"(saddr), "l"(gmem_src));
}
__device__ __forceinline__ void cp_async_commit() { asm volatile("cp.async.commit_group;"); }
__device__ __forceinline__ void cp_async_wait0()  { asm volatile("cp.async.wait_group 0;" ::: "memory"); }

// ---------------- mma.sync helpers (sm_80-era PTX; valid on compute_103) ---------
__device__ __forceinline__ void ldsm_x4(unsigned addr, unsigned* r)
{
    asm volatile("ldmatrix.sync.aligned.m8n8.x4.shared.b16 {%0,%1,%2,%3}, [%4];"
                 : "=r"(r[0]), "=r"(r[1]), "=r"(r[2]), "=r"(r[3]) : "r"(addr));
}
__device__ __forceinline__ void ldsm_x2(unsigned addr, unsigned* r)
{
    asm volatile("ldmatrix.sync.aligned.m8n8.x2.shared.b16 {%0,%1}, [%2];"
                 : "=r"(r[0]), "=r"(r[1]) : "r"(addr));
}
__device__ __forceinline__ void mma_bf16(float* c, const unsigned* a, const unsigned* b)
{
    asm volatile("mma.sync.aligned.m16n8k16.row.col.f32.bf16.bf16.f32 "
                 "{%0,%1,%2,%3}, {%4,%5,%6,%7}, {%8,%9}, {%0,%1,%2,%3};"
                 : "+f"(c[0]), "+f"(c[1]), "+f"(c[2]), "+f"(c[3])
                 : "r"(a[0]), "r"(a[1]), "r"(a[2]), "r"(a[3]),
                   "r"(b[0]), "r"(b[1]));
}

// ---------------- bf16 pack/unpack helpers ----------------
__device__ __forceinline__ unsigned pack_bf16(__nv_bfloat16 a, __nv_bfloat16 b)
{
    return (unsigned)__bfloat16_as_ushort(a) | ((unsigned)__bfloat16_as_ushort(b) << 16);
}
__device__ __forceinline__ unsigned packf(float x, float y)
{
    return pack_bf16(__float2bfloat16(x), __float2bfloat16(y));
}
__device__ __forceinline__ float2 bf2f(unsigned u)
{
    __nv_bfloat162 b = *reinterpret_cast<__nv_bfloat162*>(&u);
    return __bfloat1622float2(b);
}

__global__ void convA_kernel(const float* __restrict__ X, unsigned* __restrict__ Abf, int n2)
{
    int i = blockIdx.x * blockDim.x + threadIdx.x;
    if (i >= n2) return;
    float2 x = ((const float2*)X)[i];
    Abf[i] = packf(x.x, x.y);
}

struct WPtrs { const float* W[4]; };

// transpose W[K,256] -> Wt[256,K] (K-major rows), bf16 packed
__global__ void convW_kernel(WPtrs wp, unsigned* __restrict__ Wtbf, int K)
{
    __shared__ float t[32][33];
    int wi = blockIdx.z;
    const float* __restrict__ W = wp.W[wi];
    int n0 = blockIdx.x * 32, k0 = blockIdx.y * 32;
    for (int r = threadIdx.y; r < 32; r += 8)
        t[r][threadIdx.x] = W[(size_t)(k0 + r) * D1 + n0 + threadIdx.x];
    __syncthreads();
    int tid2 = threadIdx.y * 32 + threadIdx.x;
    int K2 = K >> 1;
    for (int i = tid2; i < 32 * 16; i += 256) {
        int n = i >> 4, kp = i & 15;
        size_t o = (size_t)(wi * D1 + n0 + n) * K2 + (k0 >> 1) + kp;
        Wtbf[o] = packf(t[2 * kp][n], t[2 * kp + 1][n]);
    }
}

// ---------------- HMMA GEMM: C[wi][M,256] = A[M,K] @ W[wi][K,256] + b ------------
// Outputs: fp32 (q, skip) or packed-bf16 rows with stride 256 u32 (k, v -> kv table).
struct TCOut {
    const float* bias[4];
    float*       C[4];
    unsigned*    Cb[4];
};

#define ROWB   48
#define SECB   (128 * ROWB)      // 6144
#define CHUNKB (2 * SECB)        // 12288
#define SMEM_MMA (2 * CHUNKB)    // 24576

__global__ __launch_bounds__(256)
void gemm_mma_kernel(const unsigned* __restrict__ Abf, const unsigned* __restrict__ Wtbf,
                     TCOut pr, int M, int K)
{
    extern __shared__ __align__(16) char smem[];
    const int tid = threadIdx.x, lane = tid & 31, wid = tid >> 5;
    const int bm = blockIdx.x, wi = blockIdx.y >> 1, bn = blockIdx.y & 1;
    const int warp_m = wid & 1, warp_n = wid >> 1;
    const int K2 = K >> 1, nkb = K >> 4;
    const unsigned sbase = (unsigned)__cvta_generic_to_shared(smem);

    // per-thread cp.async mapping: 2 x 16B per chunk (A: 256 ops, B: 256 ops)
    const unsigned* gptr[2];
    unsigned sdst[2];
#pragma unroll
    for (int t = 0; t < 2; t++) {
        int id = tid + t * 256;
        int sec = id >> 8, sid = id & 255, row = sid >> 1, q = sid & 1;
        sdst[t] = sec * SECB + row * ROWB + q * 16;
        if (sec == 0) {
            int grow = bm * 128 + row;
            if (grow >= M) grow = M - 1;          // clamp: OOB rows never stored
            gptr[t] = Abf + (size_t)grow * K2 + q * 4;
        } else {
            int n = bn * 128 + row;
            gptr[t] = Wtbf + (size_t)(wi * D1 + n) * K2 + q * 4;
        }
    }

    unsigned aA[4], aB[4];
#pragma unroll
    for (int i = 0; i < 4; i++) {
        unsigned arow = warp_m * 64 + i * 16 + (lane & 15);
        aA[i] = sbase + arow * ROWB + ((lane >> 4) << 4);
        unsigned brow = warp_n * 32 + i * 8 + (lane & 7);
        aB[i] = sbase + SECB + brow * ROWB + (((lane >> 3) & 1) << 4);
    }

    float acc[4][4][4];
#pragma unroll
    for (int i = 0; i < 4; i++)
#pragma unroll
        for (int j = 0; j < 4; j++)
#pragma unroll
            for (int e = 0; e < 4; e++) acc[i][j][e] = 0.f;

#pragma unroll
    for (int t = 0; t < 2; t++) cp_async16(smem + sdst[t], gptr[t]);
    cp_async_commit();

    for (int kb = 0; kb < nkb; kb++) {
        const int cur = kb & 1;
        cp_async_wait0();
        __syncthreads();
        if (kb + 1 < nkb) {
            const unsigned bo = (cur ^ 1) * CHUNKB;
            const int go = (kb + 1) * 8;          // 8 u32 = 32B per chunk per row
#pragma unroll
            for (int t = 0; t < 2; t++)
                cp_async16(smem + bo + sdst[t], gptr[t] + go);
            cp_async_commit();
        }

        const unsigned bo = cur * CHUNKB;
        unsigned Af[4][4], Bf[4][2];
#pragma unroll
        for (int i = 0; i < 4; i++) {
            ldsm_x4(aA[i] + bo, Af[i]);
            ldsm_x2(aB[i] + bo, Bf[i]);
        }
#pragma unroll
        for (int i = 0; i < 4; i++)
#pragma unroll
            for (int j = 0; j < 4; j++)
                mma_bf16(acc[i][j], Af[i], Bf[j]);
        __syncthreads();
    }

    const float* __restrict__ bias = pr.bias[wi];
    const int colbase = bn * 128 + warp_n * 32;
    unsigned* __restrict__ Cb = pr.Cb[wi];
    if (Cb) {
        // bf16 packed output into kv table (row stride 256 u32)
#pragma unroll
        for (int j = 0; j < 4; j++) {
            int c0 = colbase + j * 8 + (lane & 3) * 2;
            float bx = bias[c0], by = bias[c0 + 1];
#pragma unroll
            for (int i = 0; i < 4; i++) {
                int r0 = bm * 128 + warp_m * 64 + i * 16 + (lane >> 2);
                if (r0 < M)
                    Cb[(size_t)r0 * D1 + (c0 >> 1)] =
                        packf(acc[i][j][0] + bx, acc[i][j][1] + by);
                int r1 = r0 + 8;
                if (r1 < M)
                    Cb[(size_t)r1 * D1 + (c0 >> 1)] =
                        packf(acc[i][j][2] + bx, acc[i][j][3] + by);
            }
        }
    } else {
        float* __restrict__ C = pr.C[wi];
#pragma unroll
        for (int j = 0; j < 4; j++) {
            int c0 = colbase + j * 8 + (lane & 3) * 2;
            float bx = bias[c0], by = bias[c0 + 1];
#pragma unroll
            for (int i = 0; i < 4; i++) {
                int r0 = bm * 128 + warp_m * 64 + i * 16 + (lane >> 2);
                if (r0 < M) {
                    float2 o = make_float2(acc[i][j][0] + bx, acc[i][j][1] + by);
                    *(float2*)(C + (size_t)r0 * D1 + c0) = o;
                }
                int r1 = r0 + 8;
                if (r1 < M) {
                    float2 o = make_float2(acc[i][j][2] + bx, acc[i][j][3] + by);
                    *(float2*)(C + (size_t)r1 * D1 + c0) = o;
                }
            }
        }
    }
}

// ---------------- CSR build (by dst), once per launch ----------------
__global__ void zero_deg_kernel(int* deg)
{
    int i = blockIdx.x * blockDim.x + threadIdx.x;
    if (i < NN) deg[i] = 0;
}

__global__ void hist_kernel(const int* __restrict__ dst, int* __restrict__ deg)
{
    int e = blockIdx.x * blockDim.x + threadIdx.x;
    if (e < EE) atomicAdd(&deg[dst[e]], 1);
}

__global__ void scan_kernel(const int* __restrict__ deg, int* __restrict__ off,
                            int* __restrict__ cur)
{
    __shared__ int sums[1024];
    const int C = (NN + 1023) / 1024;
    int t = threadIdx.x;
    int b0 = t * C, b1 = min(b0 + C, NN);
    int s = 0;
    for (int i = b0; i < b1; i++) s += deg[i];
    sums[t] = s;
    __syncthreads();
    for (int st = 1; st < 1024; st <<= 1) {
        int v = (t >= st) ? sums[t - st] : 0;
        __syncthreads();
        sums[t] += v;
        __syncthreads();
    }
    int base = (t == 0) ? 0 : sums[t - 1];
    for (int i = b0; i < b1; i++) {
        off[i] = base;
        cur[i] = base;
        base += deg[i];
    }
    if (t == 1023) off[NN] = sums[1023];
}

__global__ void fill_kernel(const int* __restrict__ src, const int* __restrict__ dst,
                            int* __restrict__ cur, int* __restrict__ csrc)
{
    int e = blockIdx.x * blockDim.x + threadIdx.x;
    if (e >= EE) return;
    int d = dst[e];
    int pos = atomicAdd(&cur[d], 1);
    csrc[pos] = src[e];
}

// ---------------- fused node-centric attention (bf16 kv gathers) ----------------
// one warp per node; 2-deep register prefetch. kv rows interleaved (1KB/node):
// k at u32 offset 0, v at offset 128. One uint4 per lane per half.
__global__ __launch_bounds__(256)
void attn_kernel(const float* __restrict__ q, const unsigned* __restrict__ kvbf,
                 const float* __restrict__ skip,
                 const int* __restrict__ off, const int* __restrict__ csrc,
                 float* __restrict__ out,
                 unsigned* __restrict__ Abf, int write_split)
{
    int node = (blockIdx.x * blockDim.x + threadIdx.x) >> 5;
    if (node >= NN) return;
    int lane = threadIdx.x & 31;

    const float4* qp = (const float4*)(q + (size_t)node * D1) + lane * 2;
    float4 qa = qp[0], qb = qp[1];
    const float4* sp = (const float4*)(skip + (size_t)node * D1) + lane * 2;
    float4 sa = sp[0], sb = sp[1];

    float n0 = 0.f, n1 = 0.f, n2 = 0.f, n3 = 0.f;
    float n4 = 0.f, n5 = 0.f, n6 = 0.f, n7 = 0.f;
    float den = 0.f;

    const int beg = off[node], end = off[node + 1];
    const int last = end - 1;

    uint4 kw, vw;
    if (beg < end) {
        int s = csrc[beg];
        const uint4* base = (const uint4*)(kvbf + (size_t)s * D1);
        kw = base[lane];
        vw = base[32 + lane];
    }

    for (int p = beg; p < end; ++p) {
        int pn = (p + 1 < end) ? (p + 1) : last;
        int s2 = csrc[pn];
        const uint4* base2 = (const uint4*)(kvbf + (size_t)s2 * D1);
        uint4 kw2 = base2[lane];
        uint4 vw2 = base2[32 + lane];

        float2 k0 = bf2f(kw.x), k1 = bf2f(kw.y), k2 = bf2f(kw.z), k3 = bf2f(kw.w);
        float d = qa.x * k0.x + qa.y * k0.y + qa.z * k1.x + qa.w * k1.y
                + qb.x * k2.x + qb.y * k2.y + qb.z * k3.x + qb.w * k3.y;
        d += __shfl_xor_sync(0xffffffffu, d, 1);
        d += __shfl_xor_sync(0xffffffffu, d, 2);
        d += __shfl_xor_sync(0xffffffffu, d, 4);
        float ex = __expf(d * 0.125f);   // 1/sqrt(64)
        float2 v0 = bf2f(vw.x), v1 = bf2f(vw.y), v2 = bf2f(vw.z), v3 = bf2f(vw.w);
        n0 += ex * v0.x; n1 += ex * v0.y; n2 += ex * v1.x; n3 += ex * v1.y;
        n4 += ex * v2.x; n5 += ex * v2.y; n6 += ex * v3.x; n7 += ex * v3.y;
        den += ex;

        kw = kw2; vw = vw2;
    }

    float inv = (end > beg) ? 1.f / den : 0.f;
    float4 oa, ob;
    oa.x = eluf(n0 * inv + sa.x);
    oa.y = eluf(n1 * inv + sa.y);
    oa.z = eluf(n2 * inv + sa.z);
    oa.w = eluf(n3 * inv + sa.w);
    ob.x = eluf(n4 * inv + sb.x);
    ob.y = eluf(n5 * inv + sb.y);
    ob.z = eluf(n6 * inv + sb.z);
    ob.w = eluf(n7 * inv + sb.w);
    float4* op = (float4*)(out + (size_t)node * D1) + lane * 2;
    op[0] = oa;
    op[1] = ob;

    if (write_split) {
        // packed bf16 rows for next layer's GEMM (K-contiguous, 2 bf16/u32)
        uint4 h4;
        h4.x = packf(oa.x, oa.y);
        h4.y = packf(oa.z, oa.w);
        h4.z = packf(ob.x, ob.y);
        h4.w = packf(ob.z, ob.w);
        *(uint4*)(Abf + (size_t)node * (D1 / 2) + lane * 4) = h4;
    }
}

// ---------------- pooling ----------------
__global__ void zero_pool_kernel(float* pool, float* cnt)
{
    int i = blockIdx.x * blockDim.x + threadIdx.x;
    if (i < GG * D1) pool[i] = 0.f;
    if (i < GG) cnt[i] = 0.f;
}

__global__ void count_kernel(const int* __restrict__ batch, float* __restrict__ cnt)
{
    int n = blockIdx.x * blockDim.x + threadIdx.x;
    if (n < NN) atomicAdd(&cnt[batch[n]], 1.0f);
}

__global__ void pool_kernel(const float* __restrict__ h, const int* __restrict__ batch,
                            float* __restrict__ pool)
{
    int n0 = blockIdx.x * 64;
    if (n0 >= NN) return;
    int c = threadIdx.x;
    float acc = 0.f;
    int curg = batch[n0];
    for (int i = 0; i < 64; i++) {
        int n = n0 + i;
        if (n >= NN) break;
        int g = batch[n];
        if (g != curg) {
            atomicAdd(&pool[(size_t)curg * D1 + c], acc);
            acc = 0.f;
            curg = g;
        }
        acc += h[(size_t)n * D1 + c];
    }
    atomicAdd(&pool[(size_t)curg * D1 + c], acc);
}

// ---------------- classifier + log_softmax ----------------
__global__ void final_kernel(const float* __restrict__ pool, const float* __restrict__ cnt,
                             const float* __restrict__ Wl, const float* __restrict__ bl,
                             float* __restrict__ out)
{
    int g = blockIdx.x, t = threadIdx.x;
    __shared__ float red[256];
    __shared__ float logits[OUTC + 1];
    float invc = 1.0f / fmaxf(cnt[g], 1.0f);
    float p = pool[(size_t)g * D1 + t] * invc;
    for (int o = 0; o < OUTC; o++) {
        red[t] = p * Wl[t * OUTC + o];
        __syncthreads();
        for (int st = 128; st > 0; st >>= 1) {
            if (t < st) red[t] += red[t + st];
            __syncthreads();
        }
        if (t == 0) logits[o] = red[0] + bl[o];
        __syncthreads();
    }
    if (t == 0) {
        float m = -1e30f;
        for (int o = 0; o < OUTC; o++) m = fmaxf(m, logits[o]);
        float s = 0.f;
        for (int o = 0; o < OUTC; o++) s += expf(logits[o] - m);
        logits[OUTC] = m + logf(s);
    }
    __syncthreads();
    if (t < OUTC) out[g * OUTC + t] = logits[t] - logits[OUTC];
}

// ---------------- host-side orchestration ----------------
static void run_layer_mma(int K,
                          const float* Wq, const float* bq, const float* Wk, const float* bk,
                          const float* Wv, const float* bv, const float* Ws, const float* bs,
                          const int* off, const int* csrc,
                          unsigned* Abf, unsigned* Wtbf,
                          float* q, unsigned* kvbf, float* skip, float* hout,
                          int write_split)
{
    WPtrs wp; wp.W[0] = Wq; wp.W[1] = Wk; wp.W[2] = Wv; wp.W[3] = Ws;
    convW_kernel<<<dim3(D1 / 32, K / 32, 4), dim3(32, 8)>>>(wp, Wtbf, K);

    TCOut pr;
    pr.bias[0] = bq; pr.bias[1] = bk; pr.bias[2] = bv; pr.bias[3] = bs;
    pr.C[0] = q;       pr.C[1] = nullptr;   pr.C[2] = nullptr;      pr.C[3] = skip;
    pr.Cb[0] = nullptr; pr.Cb[1] = kvbf;    pr.Cb[2] = kvbf + 128;  pr.Cb[3] = nullptr;
    gemm_mma_kernel<<<dim3((NN + 127) / 128, 8), 256, SMEM_MMA>>>(
        Abf, Wtbf, pr, NN, K);

    attn_kernel<<<(NN * 32 + 255) / 256, 256>>>(q, kvbf, skip, off, csrc,
                                                hout, Abf, write_split);
}

extern "C" void kernel_launch(void* const* d_in, const int* in_sizes, int n_in,
                              void* d_out, int out_size)
{
    const float* x     = (const float*)d_in[0];
    const int*   ei    = (const int*)d_in[1];
    const int*   batch = (const int*)d_in[2];
    const float* Wq1 = (const float*)d_in[3],  *bq1 = (const float*)d_in[4];
    const float* Wk1 = (const float*)d_in[5],  *bk1 = (const float*)d_in[6];
    const float* Wv1 = (const float*)d_in[7],  *bv1 = (const float*)d_in[8];
    const float* Ws1 = (const float*)d_in[9],  *bs1 = (const float*)d_in[10];
    const float* Wq2 = (const float*)d_in[11], *bq2 = (const float*)d_in[12];
    const float* Wk2 = (const float*)d_in[13], *bk2 = (const float*)d_in[14];
    const float* Wv2 = (const float*)d_in[15], *bv2 = (const float*)d_in[16];
    const float* Ws2 = (const float*)d_in[17], *bs2 = (const float*)d_in[18];
    const float* Wl  = (const float*)d_in[19], *bl  = (const float*)d_in[20];
    float* out = (float*)d_out;

    const int* src = ei;
    const int* dst = ei + EE;

    float *q, *skip, *h, *pool, *cnt;
    int *deg, *off, *cur, *csrc;
    unsigned *kvbf, *Abf, *Wtbf;
    cudaGetSymbolAddress((void**)&q,    g_q);
    cudaGetSymbolAddress((void**)&skip, g_skip);
    cudaGetSymbolAddress((void**)&h,    g_h);
    cudaGetSymbolAddress((void**)&kvbf, g_kvbf);
    cudaGetSymbolAddress((void**)&deg,  g_deg);
    cudaGetSymbolAddress((void**)&off,  g_off);
    cudaGetSymbolAddress((void**)&cur,  g_cur);
    cudaGetSymbolAddress((void**)&csrc, g_csrc);
    cudaGetSymbolAddress((void**)&pool, g_pool);
    cudaGetSymbolAddress((void**)&cnt,  g_cnt);
    cudaGetSymbolAddress((void**)&Abf,  g_Abf);
    cudaGetSymbolAddress((void**)&Wtbf, g_Wtbf);

    // CSR build (shared by both layers)
    zero_deg_kernel<<<(NN + 255) / 256, 256>>>(deg);
    hist_kernel<<<(EE + 255) / 256, 256>>>(dst, deg);
    scan_kernel<<<1, 1024>>>(deg, off, cur);
    fill_kernel<<<(EE + 255) / 256, 256>>>(src, dst, cur, csrc);

    // layer 1: convert x to bf16, GEMM, attn (attn emits bf16 h for layer 2)
    {
        int n2 = NN * INC / 2;
        convA_kernel<<<(n2 + 255) / 256, 256>>>(x, Abf, n2);
    }
    run_layer_mma(INC, Wq1, bq1, Wk1, bk1, Wv1, bv1, Ws1, bs1,
                  off, csrc, Abf, Wtbf, q, kvbf, skip, h, 1);
    // layer 2: GEMM reads the bf16 h emitted by layer-1 attn
    run_layer_mma(D1, Wq2, bq2, Wk2, bk2, Wv2, bv2, Ws2, bs2,
                  off, csrc, Abf, Wtbf, q, kvbf, skip, h, 0);

    // mean pool per graph + classifier
    zero_pool_kernel<<<(GG * D1 + 255) / 256, 256>>>(pool, cnt);
    count_kernel<<<(NN + 255) / 256, 256>>>(batch, cnt);
    pool_kernel<<<(NN + 63) / 64, 256>>>(h, batch, pool);
    final_kernel<<<GG, 256>>>(pool, cnt, Wl, bl, out);
}